// round 7
// baseline (speedup 1.0000x reference)
#include <cuda_runtime.h>
#include <cuda_bf16.h>
#include <math.h>
#include <stdint.h>

// ---------------------------------------------------------------------------
// Problem constants (fixed by the dataset)
// ---------------------------------------------------------------------------
namespace {
constexpr int NN   = 100000;   // nodes per type
constexpr int EE   = 500000;   // edges per relation
constexpr int CIN  = 128;
constexpr int COUT = 128;
constexpr int NH   = 8;
constexpr int DKH  = 16;
constexpr int DFF  = 512;
constexpr int NSCAN   = 3 * NN;
constexpr int SCAN_BS = 1024;
constexpr int SCAN_NB = (NSCAN + SCAN_BS - 1) / SCAN_BS;  // 293

constexpr int AROW = 40;    // A smem row stride in bf16 (80B = 5x16B -> ldmatrix conflict-free)
constexpr int BROW = 136;   // B smem row stride in bf16 (272B = 17x16B -> conflict-free)
// per-buffer element offsets (bf16 units)
constexpr int OFF_ALO = 128 * AROW;                    // 5120
constexpr int OFF_BHI = 2 * 128 * AROW;                // 10240
constexpr int OFF_BLO = OFF_BHI + 32 * BROW;           // 14592
constexpr int BUF_ELEMS = OFF_BLO + 32 * BROW;         // 18944 elems = 37888 B
constexpr int TG_SMEM = 2 * BUF_ELEMS * 2;             // 75776 B (double buffered)
}

// ---------------------------------------------------------------------------
// Device scratch (static globals: allocation-free rule)
// ---------------------------------------------------------------------------
__device__ float g_qa[(size_t)NN * COUT];
__device__ float g_qb[(size_t)NN * COUT];
__device__ float g_kv[3][(size_t)NN * 2 * COUT];   // per relation: [N][kp(128)|vp(128)]
__device__ float g_t[2][(size_t)NN * COUT];        // aggregated messages (a, b)
__device__ float g_x[2][(size_t)NN * COUT];        // post-LN activations
__device__ float g_ff[(size_t)NN * DFF];           // FFN hidden (reused per type)
__device__ float g_Wkv[3][CIN * 2 * COUT];         // fused (Wk@att*pri/4 | Wv@msg)
__device__ float g_bkv[3][2 * COUT];
__device__ int   g_deg[NSCAN];
__device__ int   g_off[NSCAN];
__device__ int   g_wpos[NSCAN];
__device__ int   g_csr[3 * EE];
__device__ int   g_part[512];
__device__ int   g_part_scan[512];
__device__ int   g_i32;                            // 1 => edge indices are int32

// ---------------------------------------------------------------------------
// Fused per-relation weight prep
// ---------------------------------------------------------------------------
__global__ void prep_weights(const float* __restrict__ Wk, const float* __restrict__ bk,
                             const float* __restrict__ Wv, const float* __restrict__ bv,
                             const float* __restrict__ pri, const float* __restrict__ att,
                             const float* __restrict__ msg) {
    int idx = blockIdx.x * blockDim.x + threadIdx.x;
    if (idx >= 6 * CIN * COUT) return;
    int combo = idx >> 14;
    int rem   = idx & 16383;
    int i = rem >> 7;
    int j = rem & 127;
    int r = combo >> 1;
    int kind = combo & 1;
    int t = (r == 1) ? 1 : 0;
    const float* Ws = (kind ? Wv : Wk) + (size_t)t * CIN * COUT;
    const float* bs = (kind ? bv : bk) + t * COUT;
    const float* Rm = (kind ? msg : att) + (size_t)r * NH * DKH * DKH;
    int h = j >> 4, jj = j & 15;
    float scale = kind ? 1.0f : pri[r * NH + h] * 0.25f;
    float s = 0.f;
#pragma unroll
    for (int d = 0; d < DKH; d++)
        s += Ws[(size_t)i * COUT + h * DKH + d] * Rm[h * DKH * DKH + d * DKH + jj];
    g_Wkv[r][i * 256 + kind * 128 + j] = s * scale;
    if (i == 0) {
        float b = 0.f;
#pragma unroll
        for (int d = 0; d < DKH; d++)
            b += bs[h * DKH + d] * Rm[h * DKH * DKH + d * DKH + jj];
        g_bkv[r][kind * 128 + j] = b * scale;
    }
}

// ---------------------------------------------------------------------------
// bf16 double-pseudo GEMM (3-term: HiHi + LoHi + HiLo) on mma.m16n8k16,
// ldmatrix fragments, double-buffered smem software pipeline.
// ---------------------------------------------------------------------------
__device__ __forceinline__ void mma16(float* c, const uint32_t* a, const uint32_t* b) {
    asm volatile(
        "mma.sync.aligned.m16n8k16.row.col.f32.bf16.bf16.f32 "
        "{%0,%1,%2,%3}, {%4,%5,%6,%7}, {%8,%9}, {%0,%1,%2,%3};"
        : "+f"(c[0]), "+f"(c[1]), "+f"(c[2]), "+f"(c[3])
        : "r"(a[0]), "r"(a[1]), "r"(a[2]), "r"(a[3]), "r"(b[0]), "r"(b[1]));
}

__device__ __forceinline__ void ldmx4(uint32_t* r, uint32_t saddr) {
    asm volatile("ldmatrix.sync.aligned.m8n8.x4.shared.b16 {%0,%1,%2,%3}, [%4];"
                 : "=r"(r[0]), "=r"(r[1]), "=r"(r[2]), "=r"(r[3]) : "r"(saddr));
}
__device__ __forceinline__ void ldmx4t(uint32_t* r, uint32_t saddr) {
    asm volatile("ldmatrix.sync.aligned.m8n8.x4.trans.shared.b16 {%0,%1,%2,%3}, [%4];"
                 : "=r"(r[0]), "=r"(r[1]), "=r"(r[2]), "=r"(r[3]) : "r"(saddr));
}

// split fp32x4 -> packed bf16 hi (8B) + bf16 residual (8B)
__device__ __forceinline__ void cvt_store4(__nv_bfloat16* hi, __nv_bfloat16* lo, float4 v) {
    __nv_bfloat162 h0 = __floats2bfloat162_rn(v.x, v.y);
    __nv_bfloat162 h1 = __floats2bfloat162_rn(v.z, v.w);
    __nv_bfloat162 l0 = __floats2bfloat162_rn(v.x - __bfloat162float(h0.x),
                                              v.y - __bfloat162float(h0.y));
    __nv_bfloat162 l1 = __floats2bfloat162_rn(v.z - __bfloat162float(h1.x),
                                              v.w - __bfloat162float(h1.y));
    uint2 hp, lp;
    hp.x = *reinterpret_cast<uint32_t*>(&h0); hp.y = *reinterpret_cast<uint32_t*>(&h1);
    lp.x = *reinterpret_cast<uint32_t*>(&l0); lp.y = *reinterpret_cast<uint32_t*>(&l1);
    *reinterpret_cast<uint2*>(hi) = hp;
    *reinterpret_cast<uint2*>(lo) = lp;
}

template<bool RELU_A, bool RELU_OUT, bool RES>
__global__ __launch_bounds__(256, 2) void tgemm(
        const float* __restrict__ A, const float* __restrict__ B,
        const float* __restrict__ bias, const float* __restrict__ Rp,
        float* __restrict__ C, int M, int Ncols, int K) {
    extern __shared__ __align__(16) __nv_bfloat16 dsm[];

    int tid = threadIdx.x;
    int wid = tid >> 5, lane = tid & 31;
    int wm = wid & 3, wn = wid >> 2;       // 4x2 warp grid, warp tile 32x64
    int wrow = wm * 32, wcol = wn * 64;
    int row0 = blockIdx.y * 128;
    int col0 = blockIdx.x * 128;

    float acc[2][8][4];
#pragma unroll
    for (int mt = 0; mt < 2; mt++)
#pragma unroll
        for (int nt = 0; nt < 8; nt++)
#pragma unroll
            for (int r = 0; r < 4; r++) acc[mt][nt][r] = 0.f;

    // staging: A thread -> (row tid>>1, 16 cols), B -> (row tid>>3, 16 cols)
    const int arow = tid >> 1;
    const int acol = (tid & 1) * 16;
    const int brow = tid >> 3;
    const int bcol = (tid & 7) * 16;
    const int agr  = row0 + arow;

    // per-thread ldmatrix base offsets
    const int lrow = (lane & 7) + ((lane >> 3) & 1) * 8;   // row within 16
    const int lcol = (lane >> 4) * 8;                      // col 8-offset
    const uint32_t smem_base = (uint32_t)__cvta_generic_to_shared(dsm);

    float4 a_st[4], b_st[4];
    // load tile 0
    if (agr < M) {
#pragma unroll
        for (int i = 0; i < 4; i++) {
            float4 v = *reinterpret_cast<const float4*>(A + (size_t)agr * K + acol + 4 * i);
            if (RELU_A) {
                v.x = fmaxf(v.x, 0.f); v.y = fmaxf(v.y, 0.f);
                v.z = fmaxf(v.z, 0.f); v.w = fmaxf(v.w, 0.f);
            }
            a_st[i] = v;
        }
    } else {
#pragma unroll
        for (int i = 0; i < 4; i++) a_st[i] = make_float4(0.f, 0.f, 0.f, 0.f);
    }
#pragma unroll
    for (int i = 0; i < 4; i++)
        b_st[i] = *reinterpret_cast<const float4*>(B + (size_t)brow * Ncols + col0 + bcol + 4 * i);

    // stage tile 0 into buffer 0
#pragma unroll
    for (int i = 0; i < 4; i++) {
        int ai = arow * AROW + acol + 4 * i;
        int bi = brow * BROW + bcol + 4 * i;
        cvt_store4(dsm + ai, dsm + OFF_ALO + ai, a_st[i]);
        cvt_store4(dsm + OFF_BHI + bi, dsm + OFF_BLO + bi, b_st[i]);
    }
    __syncthreads();

    const int n_tiles = K >> 5;
    for (int t = 0; t < n_tiles; t++) {
        const int buf = t & 1;
        const uint32_t cur = smem_base + (uint32_t)buf * (BUF_ELEMS * 2);
        const bool have_next = (t + 1 < n_tiles);
        const int kk_next = (t + 1) * 32;

        // issue next-tile global loads (latency hidden under MMA phase)
        if (have_next) {
            if (agr < M) {
#pragma unroll
                for (int i = 0; i < 4; i++) {
                    float4 v = *reinterpret_cast<const float4*>(A + (size_t)agr * K + kk_next + acol + 4 * i);
                    if (RELU_A) {
                        v.x = fmaxf(v.x, 0.f); v.y = fmaxf(v.y, 0.f);
                        v.z = fmaxf(v.z, 0.f); v.w = fmaxf(v.w, 0.f);
                    }
                    a_st[i] = v;
                }
            }
#pragma unroll
            for (int i = 0; i < 4; i++)
                b_st[i] = *reinterpret_cast<const float4*>(B + (size_t)(kk_next + brow) * Ncols + col0 + bcol + 4 * i);
        }

        // MMA phase from current buffer
#pragma unroll
        for (int kc = 0; kc < 2; kc++) {           // two k16 chunks per tile
            const int k0 = kc * 16;
            uint32_t ahi[2][4], alo[2][4];
#pragma unroll
            for (int mt = 0; mt < 2; mt++) {
                uint32_t off = (uint32_t)((wrow + mt * 16 + lrow) * AROW + k0 + lcol) * 2;
                ldmx4(ahi[mt], cur + off);
                ldmx4(alo[mt], cur + OFF_ALO * 2 + off);
            }
#pragma unroll
            for (int ng = 0; ng < 4; ng++) {       // n16 groups (2 nt each)
                uint32_t bhi[4], blo[4];
                uint32_t off = (uint32_t)((k0 + lrow) * BROW + wcol + ng * 16 + lcol) * 2;
                ldmx4t(bhi, cur + OFF_BHI * 2 + off);
                ldmx4t(blo, cur + OFF_BLO * 2 + off);
#pragma unroll
                for (int mt = 0; mt < 2; mt++) {
                    mma16(acc[mt][2 * ng],     ahi[mt], bhi);
                    mma16(acc[mt][2 * ng],     alo[mt], bhi);
                    mma16(acc[mt][2 * ng],     ahi[mt], blo);
                    mma16(acc[mt][2 * ng + 1], ahi[mt], bhi + 2);
                    mma16(acc[mt][2 * ng + 1], alo[mt], bhi + 2);
                    mma16(acc[mt][2 * ng + 1], ahi[mt], blo + 2);
                }
            }
        }

        // stage next tile into the other buffer (overlaps other warps' MMAs)
        if (have_next) {
            __nv_bfloat16* nxt = dsm + (buf ^ 1) * BUF_ELEMS;
#pragma unroll
            for (int i = 0; i < 4; i++) {
                int ai = arow * AROW + acol + 4 * i;
                int bi = brow * BROW + bcol + 4 * i;
                cvt_store4(nxt + ai, nxt + OFF_ALO + ai, a_st[i]);
                cvt_store4(nxt + OFF_BHI + bi, nxt + OFF_BLO + bi, b_st[i]);
            }
        }
        __syncthreads();
    }

    // epilogue: c0/c1 at (row, col..col+1), c2/c3 at (row+8, ...)
#pragma unroll
    for (int mt = 0; mt < 2; mt++) {
#pragma unroll
        for (int nt = 0; nt < 8; nt++) {
            int gr = row0 + wrow + mt * 16 + (lane >> 2);
            int gc = col0 + wcol + nt * 8 + (lane & 3) * 2;
            float2 bb = *reinterpret_cast<const float2*>(&bias[gc]);
#pragma unroll
            for (int hh = 0; hh < 2; hh++) {
                int r = gr + hh * 8;
                if (r >= M) continue;
                float o0 = acc[mt][nt][hh * 2 + 0] + bb.x;
                float o1 = acc[mt][nt][hh * 2 + 1] + bb.y;
                if (RES) {
                    float2 rr = *reinterpret_cast<const float2*>(Rp + (size_t)r * Ncols + gc);
                    o0 += rr.x; o1 += rr.y;
                }
                if (RELU_OUT) { o0 = fmaxf(o0, 0.f); o1 = fmaxf(o1, 0.f); }
                *reinterpret_cast<float2*>(C + (size_t)r * Ncols + gc) = make_float2(o0, o1);
            }
        }
    }
}

// ---------------------------------------------------------------------------
// Edge-index helpers: dtype (int32 vs int64) detected at runtime
// ---------------------------------------------------------------------------
__global__ void zero_deg() {
    int i = blockIdx.x * blockDim.x + threadIdx.x;
    if (i == 0) g_i32 = 0;
    if (i < NSCAN) g_deg[i] = 0;
}

__global__ void detect_i32(const int* __restrict__ d) {
    int i = blockIdx.x * blockDim.x + threadIdx.x;
    if (i >= EE / 2) return;
    if (d[2 * i + 1] != 0) g_i32 = 1;
}

__device__ __forceinline__ int eidx(const void* p, int i, int is32) {
    return is32 ? ((const int*)p)[i] : (int)((const long long*)p)[i];
}

__global__ void count_deg(const void* __restrict__ dst, int r) {
    int i = blockIdx.x * blockDim.x + threadIdx.x;
    if (i >= EE) return;
    int is32 = g_i32;
    atomicAdd(&g_deg[r * NN + eidx(dst, i, is32)], 1);
}

__global__ void scatter_edges(const void* __restrict__ src, const void* __restrict__ dst, int r) {
    int i = blockIdx.x * blockDim.x + threadIdx.x;
    if (i >= EE) return;
    int is32 = g_i32;
    int d = eidx(dst, i, is32);
    int p = atomicAdd(&g_wpos[r * NN + d], 1);
    g_csr[p] = eidx(src, i, is32);
}

// ---------------------------------------------------------------------------
// Exclusive scan over g_deg[3N]
// ---------------------------------------------------------------------------
__global__ void scan1() {
    __shared__ int sh[SCAN_BS];
    int i = blockIdx.x * SCAN_BS + threadIdx.x;
    sh[threadIdx.x] = (i < NSCAN) ? g_deg[i] : 0;
    __syncthreads();
    for (int ofs = SCAN_BS / 2; ofs > 0; ofs >>= 1) {
        if (threadIdx.x < ofs) sh[threadIdx.x] += sh[threadIdx.x + ofs];
        __syncthreads();
    }
    if (threadIdx.x == 0) g_part[blockIdx.x] = sh[0];
}

__global__ void scan2() {
    __shared__ int a[512], b[512];
    int t = threadIdx.x;
    int v = (t < SCAN_NB) ? g_part[t] : 0;
    a[t] = v; __syncthreads();
    int* s = a; int* d = b;
    for (int ofs = 1; ofs < 512; ofs <<= 1) {
        int x = s[t];
        if (t >= ofs) x += s[t - ofs];
        d[t] = x; __syncthreads();
        int* tmp = s; s = d; d = tmp;
    }
    g_part_scan[t] = s[t] - v;
}

__global__ void scan3() {
    __shared__ int a[SCAN_BS], b[SCAN_BS];
    int t = threadIdx.x;
    int i = blockIdx.x * SCAN_BS + t;
    int v = (i < NSCAN) ? g_deg[i] : 0;
    a[t] = v; __syncthreads();
    int* s = a; int* d = b;
    for (int ofs = 1; ofs < SCAN_BS; ofs <<= 1) {
        int x = s[t];
        if (t >= ofs) x += s[t - ofs];
        d[t] = x; __syncthreads();
        int* tmp = s; s = d; d = tmp;
    }
    if (i < NSCAN) {
        int excl = s[t] - v + g_part_scan[blockIdx.x];
        g_off[i]  = excl;
        g_wpos[i] = excl;
    }
}

// ---------------------------------------------------------------------------
// Dst-centric attention aggregation: one warp per destination node.
// ---------------------------------------------------------------------------
__device__ __forceinline__ void rel_accum(int node, int lane, int r,
                                          const float* __restrict__ kvbuf,
                                          float4 q, float4& res) {
    int off = g_off[r * NN + node];
    int dg  = g_deg[r * NN + node];
    float4 acc = make_float4(0.f, 0.f, 0.f, 0.f);
    float z = 0.f;
    int e = 0;
    for (; e + 2 <= dg; e += 2) {
        int s0 = g_csr[off + e];
        int s1 = g_csr[off + e + 1];
        const float4* kv0 = reinterpret_cast<const float4*>(kvbuf + (size_t)s0 * 256);
        const float4* kv1 = reinterpret_cast<const float4*>(kvbuf + (size_t)s1 * 256);
        float4 kp0 = kv0[lane];
        float4 kp1 = kv1[lane];
        float4 vp0 = kv0[32 + lane];
        float4 vp1 = kv1[32 + lane];
        float p0 = q.x * kp0.x + q.y * kp0.y + q.z * kp0.z + q.w * kp0.w;
        float p1 = q.x * kp1.x + q.y * kp1.y + q.z * kp1.z + q.w * kp1.w;
        p0 += __shfl_xor_sync(0xffffffffu, p0, 1);
        p1 += __shfl_xor_sync(0xffffffffu, p1, 1);
        p0 += __shfl_xor_sync(0xffffffffu, p0, 2);
        p1 += __shfl_xor_sync(0xffffffffu, p1, 2);
        float e0 = expf(p0), e1 = expf(p1);
        z += e0 + e1;
        acc.x += e0 * vp0.x + e1 * vp1.x;
        acc.y += e0 * vp0.y + e1 * vp1.y;
        acc.z += e0 * vp0.z + e1 * vp1.z;
        acc.w += e0 * vp0.w + e1 * vp1.w;
    }
    if (e < dg) {
        int s = g_csr[off + e];
        const float4* kv = reinterpret_cast<const float4*>(kvbuf + (size_t)s * 256);
        float4 kp = kv[lane];
        float4 vp = kv[32 + lane];
        float p = q.x * kp.x + q.y * kp.y + q.z * kp.z + q.w * kp.w;
        p += __shfl_xor_sync(0xffffffffu, p, 1);
        p += __shfl_xor_sync(0xffffffffu, p, 2);
        float eh = expf(p);
        z += eh;
        acc.x += eh * vp.x; acc.y += eh * vp.y;
        acc.z += eh * vp.z; acc.w += eh * vp.w;
    }
    if (z > 0.f) {
        float inv = 1.f / z;
        res.x += acc.x * inv; res.y += acc.y * inv;
        res.z += acc.z * inv; res.w += acc.w * inv;
    }
}

__global__ void agg_type_b() {   // relation 0: a -> b
    int w = (blockIdx.x * blockDim.x + threadIdx.x) >> 5;
    if (w >= NN) return;
    int lane = threadIdx.x & 31;
    float4 q = *reinterpret_cast<const float4*>(g_qb + (size_t)w * 128 + lane * 4);
    float4 res = make_float4(0.f, 0.f, 0.f, 0.f);
    rel_accum(w, lane, 0, g_kv[0], q, res);
    *reinterpret_cast<float4*>(g_t[1] + (size_t)w * 128 + lane * 4) = res;
}

__global__ void agg_type_a() {   // relations 1 (b->a) + 2 (a->a), summed
    int w = (blockIdx.x * blockDim.x + threadIdx.x) >> 5;
    if (w >= NN) return;
    int lane = threadIdx.x & 31;
    float4 q = *reinterpret_cast<const float4*>(g_qa + (size_t)w * 128 + lane * 4);
    float4 res = make_float4(0.f, 0.f, 0.f, 0.f);
    rel_accum(w, lane, 1, g_kv[1], q, res);
    rel_accum(w, lane, 2, g_kv[2], q, res);
    *reinterpret_cast<float4*>(g_t[0] + (size_t)w * 128 + lane * 4) = res;
}

// ---------------------------------------------------------------------------
// Row LayerNorm (warp per row, 128 cols)
// ---------------------------------------------------------------------------
__global__ void layernorm(float* __restrict__ X, const float* __restrict__ gamma,
                          const float* __restrict__ beta) {
    int w = (blockIdx.x * blockDim.x + threadIdx.x) >> 5;
    if (w >= NN) return;
    int lane = threadIdx.x & 31;
    float4 v = *reinterpret_cast<const float4*>(X + (size_t)w * 128 + lane * 4);
    float s  = v.x + v.y + v.z + v.w;
    float s2 = v.x * v.x + v.y * v.y + v.z * v.z + v.w * v.w;
#pragma unroll
    for (int ofs = 16; ofs > 0; ofs >>= 1) {
        s  += __shfl_xor_sync(0xffffffffu, s, ofs);
        s2 += __shfl_xor_sync(0xffffffffu, s2, ofs);
    }
    float mu   = s * (1.f / 128.f);
    float var  = s2 * (1.f / 128.f) - mu * mu;
    float rstd = rsqrtf(var + 1e-5f);
    float4 g = *reinterpret_cast<const float4*>(gamma + lane * 4);
    float4 b = *reinterpret_cast<const float4*>(beta + lane * 4);
    float4 o;
    o.x = (v.x - mu) * rstd * g.x + b.x;
    o.y = (v.y - mu) * rstd * g.y + b.y;
    o.z = (v.z - mu) * rstd * g.z + b.z;
    o.w = (v.w - mu) * rstd * g.w + b.w;
    *reinterpret_cast<float4*>(X + (size_t)w * 128 + lane * 4) = o;
}

// ---------------------------------------------------------------------------
// Launch
// ---------------------------------------------------------------------------
extern "C" void kernel_launch(void* const* d_in, const int* in_sizes, int n_in,
                              void* d_out, int out_size) {
    const float* h_a   = (const float*)d_in[0];
    const float* h_b   = (const float*)d_in[1];
    const float* Wk    = (const float*)d_in[2];
    const float* bk    = (const float*)d_in[3];
    const float* Wq    = (const float*)d_in[4];
    const float* bq    = (const float*)d_in[5];
    const float* Wv    = (const float*)d_in[6];
    const float* bv    = (const float*)d_in[7];
    const float* Wa    = (const float*)d_in[8];
    const float* ba    = (const float*)d_in[9];
    const float* gamma = (const float*)d_in[10];
    const float* beta  = (const float*)d_in[11];
    const float* W1    = (const float*)d_in[12];
    const float* b1    = (const float*)d_in[13];
    const float* W2    = (const float*)d_in[14];
    const float* b2    = (const float*)d_in[15];
    const float* pri   = (const float*)d_in[16];
    const float* att   = (const float*)d_in[17];
    const float* msg   = (const float*)d_in[18];
    const void* src0 = d_in[19]; const void* dst0 = d_in[20];
    const void* src1 = d_in[21]; const void* dst1 = d_in[22];
    const void* src2 = d_in[23]; const void* dst2 = d_in[24];
    float* out = (float*)d_out;

    float *p_qa, *p_qb, *p_kv, *p_t, *p_x, *p_ff, *p_Wkv, *p_bkv;
    cudaGetSymbolAddress((void**)&p_qa,  g_qa);
    cudaGetSymbolAddress((void**)&p_qb,  g_qb);
    cudaGetSymbolAddress((void**)&p_kv,  g_kv);
    cudaGetSymbolAddress((void**)&p_t,   g_t);
    cudaGetSymbolAddress((void**)&p_x,   g_x);
    cudaGetSymbolAddress((void**)&p_ff,  g_ff);
    cudaGetSymbolAddress((void**)&p_Wkv, g_Wkv);
    cudaGetSymbolAddress((void**)&p_bkv, g_bkv);

    // opt-in to 74KB dynamic smem (host-side attribute set; capture-safe)
    cudaFuncSetAttribute(tgemm<false,false,false>, cudaFuncAttributeMaxDynamicSharedMemorySize, TG_SMEM);
    cudaFuncSetAttribute(tgemm<true,false,true>,   cudaFuncAttributeMaxDynamicSharedMemorySize, TG_SMEM);
    cudaFuncSetAttribute(tgemm<false,true,false>,  cudaFuncAttributeMaxDynamicSharedMemorySize, TG_SMEM);

    const int gy = (NN + 127) / 128;           // 782
    const int eb = (EE + 255) / 256;
    const int wb = (NN * 32) / 256;            // 12500 (exact)

    // 0. reset + edge dtype detection
    zero_deg<<<(NSCAN + 255) / 256, 256>>>();
    detect_i32<<<(EE / 2 + 255) / 256, 256>>>((const int*)dst0);

    // 1. fused relation weights
    prep_weights<<<(6 * CIN * COUT + 255) / 256, 256>>>(Wk, bk, Wv, bv, pri, att, msg);

    // 2. projections (q per type; fused kp|vp per relation)
    tgemm<false,false,false><<<dim3(1, gy), 256, TG_SMEM>>>(h_a, Wq,                 bq,       nullptr, p_qa, NN, 128, 128);
    tgemm<false,false,false><<<dim3(1, gy), 256, TG_SMEM>>>(h_b, Wq + 128 * 128,     bq + 128, nullptr, p_qb, NN, 128, 128);
    tgemm<false,false,false><<<dim3(2, gy), 256, TG_SMEM>>>(h_a, p_Wkv,              p_bkv,       nullptr, p_kv,                      NN, 256, 128);
    tgemm<false,false,false><<<dim3(2, gy), 256, TG_SMEM>>>(h_b, p_Wkv + 128 * 256,  p_bkv + 256, nullptr, p_kv + (size_t)NN * 256,   NN, 256, 128);
    tgemm<false,false,false><<<dim3(2, gy), 256, TG_SMEM>>>(h_a, p_Wkv + 2*128*256,  p_bkv + 512, nullptr, p_kv + 2*(size_t)NN * 256, NN, 256, 128);

    // 3. CSR build (degree -> scan -> scatter)
    count_deg<<<eb, 256>>>(dst0, 0);
    count_deg<<<eb, 256>>>(dst1, 1);
    count_deg<<<eb, 256>>>(dst2, 2);
    scan1<<<SCAN_NB, SCAN_BS>>>();
    scan2<<<1, 512>>>();
    scan3<<<SCAN_NB, SCAN_BS>>>();
    scatter_edges<<<eb, 256>>>(src0, dst0, 0);
    scatter_edges<<<eb, 256>>>(src1, dst1, 1);
    scatter_edges<<<eb, 256>>>(src2, dst2, 2);

    // 4. attention aggregation (warp per dst node, no atomics)
    agg_type_b<<<wb, 256>>>();
    agg_type_a<<<wb, 256>>>();

    // 5. per-type update: relu(t)@Wa + ba + h -> LN -> relu(@W1+b1)@W2 + b2
    for (int t = 0; t < 2; t++) {
        const float* hres = t ? h_b : h_a;
        tgemm<true,false,true><<<dim3(1, gy), 256, TG_SMEM>>>(p_t + (size_t)t * NN * 128, Wa + (size_t)t * 128 * 128,
                                                              ba + t * 128, hres,
                                                              p_x + (size_t)t * NN * 128, NN, 128, 128);
        layernorm<<<wb, 256>>>(p_x + (size_t)t * NN * 128, gamma + t * 128, beta + t * 128);
        tgemm<false,true,false><<<dim3(4, gy), 256, TG_SMEM>>>(p_x + (size_t)t * NN * 128, W1 + (size_t)t * 128 * 512,
                                                               b1 + t * 512, nullptr, p_ff, NN, 512, 128);
        tgemm<false,false,false><<<dim3(1, gy), 256, TG_SMEM>>>(p_ff, W2 + (size_t)t * 512 * 128,
                                                                b2 + t * 128, nullptr,
                                                                out + (size_t)t * NN * 128, NN, 128, 512);
    }
}

// round 10
// speedup vs baseline: 1.2784x; 1.2784x over previous
#include <cuda_runtime.h>
#include <cuda_bf16.h>
#include <math.h>
#include <stdint.h>

// ---------------------------------------------------------------------------
// Problem constants
// ---------------------------------------------------------------------------
namespace {
constexpr int NN   = 100000;
constexpr int EE   = 500000;
constexpr int CIN  = 128;
constexpr int COUT = 128;
constexpr int NH   = 8;
constexpr int DKH  = 16;
constexpr int DFF  = 512;
constexpr int NSCAN   = 3 * NN;
constexpr int SCAN_BS = 1024;
constexpr int SCAN_NB = (NSCAN + SCAN_BS - 1) / SCAN_BS;  // 293

// GEMM tile geometry (identical MMA core to the R6 winner)
constexpr int AROW = 40;    // A smem row stride in bf16 (conflict-free ldmatrix)
constexpr int BROW = 136;   // B smem row stride in bf16 (conflict-free ldmatrix)
// tile layouts (bytes): A tile = [hi 128xAROW][lo 128xAROW] ; B tile = [hi 32xBROW][lo 32xBROW]
constexpr int A_PLANE = 128 * AROW * 2;       // 10240
constexpr int A_TILE  = 2 * A_PLANE;          // 20480
constexpr int B_PLANE = 32 * BROW * 2;        // 8704
constexpr int B_TILE  = 2 * B_PLANE;          // 17408
constexpr int BUF_BYTES = A_TILE + B_TILE;    // 37888
constexpr int TG_SMEM = 2 * BUF_BYTES;        // 75776 (double buffered)
constexpr int RB = 782;                       // row blocks of 128 covering NN

// weight image offsets (bytes)
constexpr size_t WQ0 = 0,        WQ1 = 69632;
constexpr size_t WKV0 = 139264,  WKV1 = 278528, WKV2 = 417792;
constexpr size_t WA0 = 557056,   WA1 = 626688;
constexpr size_t W10 = 696320,   W11 = 974848;
constexpr size_t W20 = 1253376,  W21 = 1531904;
constexpr size_t WIMG_TOTAL = 1810432;

constexpr size_t AIMG_K128 = (size_t)RB * 4 * A_TILE;    // 64,061,440 B
constexpr size_t AIMG_K512 = (size_t)RB * 16 * A_TILE;   // 256,245,760 B
}

// ---------------------------------------------------------------------------
// Device scratch
// ---------------------------------------------------------------------------
__device__ float g_qa[(size_t)NN * COUT];
__device__ float g_qb[(size_t)NN * COUT];
__device__ float g_kv[3][(size_t)NN * 2 * COUT];
__device__ float g_x[(size_t)NN * COUT];          // LN input (per type, reused)
__device__ float g_Wkv[3][CIN * 2 * COUT];
__device__ float g_bkv[3][2 * COUT];
__device__ __align__(16) char g_wimg[WIMG_TOTAL]; // weight B-images
__device__ __align__(16) char g_ia[AIMG_K128];    // h_a image
__device__ __align__(16) char g_ib[AIMG_K128];    // h_b image
__device__ __align__(16) char g_it[2][AIMG_K128]; // relu(t) images
__device__ __align__(16) char g_ix[AIMG_K128];    // LN output image (reused per type)
__device__ __align__(16) char g_iff[AIMG_K512];   // FFN hidden image (reused per type)
__device__ int   g_deg[NSCAN];
__device__ int   g_off[NSCAN];
__device__ int   g_wpos[NSCAN];
__device__ int   g_csr[3 * EE];
__device__ int   g_part[512];
__device__ int   g_part_scan[512];
__device__ int   g_i32;

// ---------------------------------------------------------------------------
// helpers
// ---------------------------------------------------------------------------
__device__ __forceinline__ void mma16(float* c, const uint32_t* a, const uint32_t* b) {
    asm volatile(
        "mma.sync.aligned.m16n8k16.row.col.f32.bf16.bf16.f32 "
        "{%0,%1,%2,%3}, {%4,%5,%6,%7}, {%8,%9}, {%0,%1,%2,%3};"
        : "+f"(c[0]), "+f"(c[1]), "+f"(c[2]), "+f"(c[3])
        : "r"(a[0]), "r"(a[1]), "r"(a[2]), "r"(a[3]), "r"(b[0]), "r"(b[1]));
}
__device__ __forceinline__ void ldmx4(uint32_t* r, uint32_t saddr) {
    asm volatile("ldmatrix.sync.aligned.m8n8.x4.shared.b16 {%0,%1,%2,%3}, [%4];"
                 : "=r"(r[0]), "=r"(r[1]), "=r"(r[2]), "=r"(r[3]) : "r"(saddr));
}
__device__ __forceinline__ void ldmx4t(uint32_t* r, uint32_t saddr) {
    asm volatile("ldmatrix.sync.aligned.m8n8.x4.trans.shared.b16 {%0,%1,%2,%3}, [%4];"
                 : "=r"(r[0]), "=r"(r[1]), "=r"(r[2]), "=r"(r[3]) : "r"(saddr));
}
__device__ __forceinline__ void cpa16(uint32_t smem, const char* g) {
    asm volatile("cp.async.cg.shared.global [%0], [%1], 16;" :: "r"(smem), "l"(g));
}
#define CPA_COMMIT() asm volatile("cp.async.commit_group;" ::: "memory")
#define CPA_WAIT0()  asm volatile("cp.async.wait_group 0;" ::: "memory")
#define CPA_WAIT1()  asm volatile("cp.async.wait_group 1;" ::: "memory")

__device__ __forceinline__ void split2(float a, float b, uint32_t& hi, uint32_t& lo) {
    __nv_bfloat162 h = __floats2bfloat162_rn(a, b);
    __nv_bfloat162 l = __floats2bfloat162_rn(a - __bfloat162float(h.x),
                                             b - __bfloat162float(h.y));
    hi = *reinterpret_cast<uint32_t*>(&h);
    lo = *reinterpret_cast<uint32_t*>(&l);
}

// ---------------------------------------------------------------------------
// Fused per-relation weight prep (fp32)
// ---------------------------------------------------------------------------
__global__ void prep_weights(const float* __restrict__ Wk, const float* __restrict__ bk,
                             const float* __restrict__ Wv, const float* __restrict__ bv,
                             const float* __restrict__ pri, const float* __restrict__ att,
                             const float* __restrict__ msg) {
    int idx = blockIdx.x * blockDim.x + threadIdx.x;
    if (idx >= 6 * CIN * COUT) return;
    int combo = idx >> 14;
    int rem   = idx & 16383;
    int i = rem >> 7;
    int j = rem & 127;
    int r = combo >> 1;
    int kind = combo & 1;
    int t = (r == 1) ? 1 : 0;
    const float* Ws = (kind ? Wv : Wk) + (size_t)t * CIN * COUT;
    const float* bs = (kind ? bv : bk) + t * COUT;
    const float* Rm = (kind ? msg : att) + (size_t)r * NH * DKH * DKH;
    int h = j >> 4, jj = j & 15;
    float scale = kind ? 1.0f : pri[r * NH + h] * 0.25f;
    float s = 0.f;
#pragma unroll
    for (int d = 0; d < DKH; d++)
        s += Ws[(size_t)i * COUT + h * DKH + d] * Rm[h * DKH * DKH + d * DKH + jj];
    g_Wkv[r][i * 256 + kind * 128 + j] = s * scale;
    if (i == 0) {
        float b = 0.f;
#pragma unroll
        for (int d = 0; d < DKH; d++)
            b += bs[h * DKH + d] * Rm[h * DKH * DKH + d * DKH + jj];
        g_bkv[r][kind * 128 + j] = b * scale;
    }
}

// ---------------------------------------------------------------------------
// Image builders: exact smem byte layouts (incl. padding strides)
// ---------------------------------------------------------------------------
// W[K][N] fp32 -> B image per (colblock c=n>>7, kchunk q=k>>5): [hi 32xBROW][lo]
__global__ void prep_img_w(const float* __restrict__ W, char* __restrict__ img,
                           int K, int N) {
    int idx = blockIdx.x * blockDim.x + threadIdx.x;
    if (idx >= K * N) return;
    int k = idx / N, n = idx % N;
    float v = W[idx];
    __nv_bfloat16 h = __float2bfloat16(v);
    __nv_bfloat16 l = __float2bfloat16(v - __bfloat162float(h));
    size_t tb = ((size_t)(n >> 7) * (K >> 5) + (k >> 5)) * B_TILE;
    uint32_t byte = (uint32_t)((k & 31) * BROW + (n & 127)) * 2;
    *reinterpret_cast<__nv_bfloat16*>(img + tb + byte) = h;
    *reinterpret_cast<__nv_bfloat16*>(img + tb + B_PLANE + byte) = l;
}

// X[M][K] fp32 -> A image per (rowblock rb=m>>7, kchunk q=k>>5): [hi 128xAROW][lo]
__global__ void prep_img_a(const float* __restrict__ X, char* __restrict__ img,
                           int M, int K) {
    int idx = blockIdx.x * blockDim.x + threadIdx.x;
    if (idx >= M * (K >> 1)) return;
    int m = idx / (K >> 1), kp = (idx % (K >> 1)) * 2;
    float2 v = *reinterpret_cast<const float2*>(X + (size_t)m * K + kp);
    uint32_t hi, lo;
    split2(v.x, v.y, hi, lo);
    size_t tb = ((size_t)(m >> 7) * (K >> 5) + (kp >> 5)) * A_TILE;
    uint32_t byte = (uint32_t)((m & 127) * AROW + (kp & 31)) * 2;
    *reinterpret_cast<uint32_t*>(img + tb + byte) = hi;
    *reinterpret_cast<uint32_t*>(img + tb + A_PLANE + byte) = lo;
}

// ---------------------------------------------------------------------------
// bf16 3-term GEMM: C = A@W (+bias)(+Res)(relu?) with cp.async image staging,
// double-buffered smem; inner loop pure ldmatrix + mma. OUT_IMG: write result
// as A-image (relu'd) instead of fp32 C.
// ---------------------------------------------------------------------------
template<bool RES, bool RELU_OUT, bool OUT_IMG>
__global__ __launch_bounds__(256, 2) void tgemm6(
        const char* __restrict__ AImg, const char* __restrict__ BImg,
        const float* __restrict__ bias, const float* __restrict__ Rp,
        float* __restrict__ C, char* __restrict__ OutImg,
        int M, int Ncols, int K) {
    extern __shared__ __align__(16) char dsm[];
    const uint32_t sm0 = (uint32_t)__cvta_generic_to_shared(dsm);

    const int tid = threadIdx.x;
    const int wid = tid >> 5, lane = tid & 31;
    const int wm = wid & 3, wn = wid >> 2;
    const int wrow = wm * 32, wcol = wn * 64;
    const int row0 = blockIdx.y * 128;
    const int col0 = blockIdx.x * 128;
    const int ntiles = K >> 5;

    float acc[2][8][4];
#pragma unroll
    for (int mt = 0; mt < 2; mt++)
#pragma unroll
        for (int nt = 0; nt < 8; nt++)
#pragma unroll
            for (int r = 0; r < 4; r++) acc[mt][nt][r] = 0.f;

    const int lrow = (lane & 7) + ((lane >> 3) & 1) * 8;
    const int lcol = (lane >> 4) * 8;

    const char* abase = AImg + (size_t)blockIdx.y * ntiles * A_TILE;
    const char* bbase = BImg + (size_t)blockIdx.x * ntiles * B_TILE;

    // issue tile 0
    {
        const char* as = abase;
        const char* bs = bbase;
        uint32_t dst = sm0;
#pragma unroll
        for (int i = 0; i < 10; i++) {
            int idx = tid + i * 256;
            if (idx < 1280)      cpa16(dst + idx * 16, as + idx * 16);
            else if (idx < 2368) cpa16(dst + A_TILE + (idx - 1280) * 16, bs + (idx - 1280) * 16);
        }
        CPA_COMMIT();
    }

    for (int t = 0; t < ntiles; t++) {
        const bool have_next = (t + 1 < ntiles);
        if (have_next) {
            const char* as = abase + (size_t)(t + 1) * A_TILE;
            const char* bs = bbase + (size_t)(t + 1) * B_TILE;
            uint32_t dst = sm0 + ((t + 1) & 1) * BUF_BYTES;
#pragma unroll
            for (int i = 0; i < 10; i++) {
                int idx = tid + i * 256;
                if (idx < 1280)      cpa16(dst + idx * 16, as + idx * 16);
                else if (idx < 2368) cpa16(dst + A_TILE + (idx - 1280) * 16, bs + (idx - 1280) * 16);
            }
            CPA_COMMIT();
            CPA_WAIT1();
        } else {
            CPA_WAIT0();
        }
        __syncthreads();

        const uint32_t cur = sm0 + (t & 1) * BUF_BYTES;
#pragma unroll
        for (int kc = 0; kc < 2; kc++) {
            const int k0 = kc * 16;
            uint32_t ahi[2][4], alo[2][4];
#pragma unroll
            for (int mt = 0; mt < 2; mt++) {
                uint32_t off = (uint32_t)((wrow + mt * 16 + lrow) * AROW + k0 + lcol) * 2;
                ldmx4(ahi[mt], cur + off);
                ldmx4(alo[mt], cur + A_PLANE + off);
            }
#pragma unroll
            for (int ng = 0; ng < 4; ng++) {
                uint32_t bhi[4], blo[4];
                uint32_t off = (uint32_t)((k0 + lrow) * BROW + wcol + ng * 16 + lcol) * 2;
                ldmx4t(bhi, cur + A_TILE + off);
                ldmx4t(blo, cur + A_TILE + B_PLANE + off);
#pragma unroll
                for (int mt = 0; mt < 2; mt++) {
                    mma16(acc[mt][2 * ng],     ahi[mt], bhi);
                    mma16(acc[mt][2 * ng],     alo[mt], bhi);
                    mma16(acc[mt][2 * ng],     ahi[mt], blo);
                    mma16(acc[mt][2 * ng + 1], ahi[mt], bhi + 2);
                    mma16(acc[mt][2 * ng + 1], alo[mt], bhi + 2);
                    mma16(acc[mt][2 * ng + 1], ahi[mt], blo + 2);
                }
            }
        }
        __syncthreads();
    }

    // epilogue
    const int okc = Ncols >> 5;   // out image k-chunks (when OUT_IMG)
#pragma unroll
    for (int mt = 0; mt < 2; mt++) {
#pragma unroll
        for (int nt = 0; nt < 8; nt++) {
            int gr0 = row0 + wrow + mt * 16 + (lane >> 2);
            int gc  = col0 + wcol + nt * 8 + (lane & 3) * 2;
            float2 bb = *reinterpret_cast<const float2*>(&bias[gc]);
#pragma unroll
            for (int hh = 0; hh < 2; hh++) {
                int r = gr0 + hh * 8;
                if (r >= M) continue;
                float o0 = acc[mt][nt][hh * 2 + 0] + bb.x;
                float o1 = acc[mt][nt][hh * 2 + 1] + bb.y;
                if (RES) {
                    float2 rr = *reinterpret_cast<const float2*>(Rp + (size_t)r * Ncols + gc);
                    o0 += rr.x; o1 += rr.y;
                }
                if (RELU_OUT) { o0 = fmaxf(o0, 0.f); o1 = fmaxf(o1, 0.f); }
                if (OUT_IMG) {
                    uint32_t hi, lo;
                    split2(o0, o1, hi, lo);
                    size_t tb = ((size_t)(r >> 7) * okc + (gc >> 5)) * A_TILE;
                    uint32_t byte = (uint32_t)((r & 127) * AROW + (gc & 31)) * 2;
                    *reinterpret_cast<uint32_t*>(OutImg + tb + byte) = hi;
                    *reinterpret_cast<uint32_t*>(OutImg + tb + A_PLANE + byte) = lo;
                } else {
                    *reinterpret_cast<float2*>(C + (size_t)r * Ncols + gc) = make_float2(o0, o1);
                }
            }
        }
    }
}

// ---------------------------------------------------------------------------
// Edge-index helpers
// ---------------------------------------------------------------------------
__global__ void zero_deg() {
    int i = blockIdx.x * blockDim.x + threadIdx.x;
    if (i == 0) g_i32 = 0;
    if (i < NSCAN) g_deg[i] = 0;
}
__global__ void detect_i32(const int* __restrict__ d) {
    int i = blockIdx.x * blockDim.x + threadIdx.x;
    if (i >= EE / 2) return;
    if (d[2 * i + 1] != 0) g_i32 = 1;
}
__device__ __forceinline__ int eidx(const void* p, int i, int is32) {
    return is32 ? ((const int*)p)[i] : (int)((const long long*)p)[i];
}
__global__ void count_deg(const void* __restrict__ dst, int r) {
    int i = blockIdx.x * blockDim.x + threadIdx.x;
    if (i >= EE) return;
    int is32 = g_i32;
    atomicAdd(&g_deg[r * NN + eidx(dst, i, is32)], 1);
}
__global__ void scatter_edges(const void* __restrict__ src, const void* __restrict__ dst, int r) {
    int i = blockIdx.x * blockDim.x + threadIdx.x;
    if (i >= EE) return;
    int is32 = g_i32;
    int d = eidx(dst, i, is32);
    int p = atomicAdd(&g_wpos[r * NN + d], 1);
    g_csr[p] = eidx(src, i, is32);
}

// ---------------------------------------------------------------------------
// Exclusive scan over g_deg[3N]
// ---------------------------------------------------------------------------
__global__ void scan1() {
    __shared__ int sh[SCAN_BS];
    int i = blockIdx.x * SCAN_BS + threadIdx.x;
    sh[threadIdx.x] = (i < NSCAN) ? g_deg[i] : 0;
    __syncthreads();
    for (int ofs = SCAN_BS / 2; ofs > 0; ofs >>= 1) {
        if (threadIdx.x < ofs) sh[threadIdx.x] += sh[threadIdx.x + ofs];
        __syncthreads();
    }
    if (threadIdx.x == 0) g_part[blockIdx.x] = sh[0];
}
__global__ void scan2() {
    __shared__ int a[512], b[512];
    int t = threadIdx.x;
    int v = (t < SCAN_NB) ? g_part[t] : 0;
    a[t] = v; __syncthreads();
    int* s = a; int* d = b;
    for (int ofs = 1; ofs < 512; ofs <<= 1) {
        int x = s[t];
        if (t >= ofs) x += s[t - ofs];
        d[t] = x; __syncthreads();
        int* tmp = s; s = d; d = tmp;
    }
    g_part_scan[t] = s[t] - v;
}
__global__ void scan3() {
    __shared__ int a[SCAN_BS], b[SCAN_BS];
    int t = threadIdx.x;
    int i = blockIdx.x * SCAN_BS + t;
    int v = (i < NSCAN) ? g_deg[i] : 0;
    a[t] = v; __syncthreads();
    int* s = a; int* d = b;
    for (int ofs = 1; ofs < SCAN_BS; ofs <<= 1) {
        int x = s[t];
        if (t >= ofs) x += s[t - ofs];
        d[t] = x; __syncthreads();
        int* tmp = s; s = d; d = tmp;
    }
    if (i < NSCAN) {
        int excl = s[t] - v + g_part_scan[blockIdx.x];
        g_off[i]  = excl;
        g_wpos[i] = excl;
    }
}

// ---------------------------------------------------------------------------
// Attention aggregation (warp per dst node) -> writes relu(t) A-image directly
// ---------------------------------------------------------------------------
__device__ __forceinline__ void rel_accum(int node, int lane, int r,
                                          const float* __restrict__ kvbuf,
                                          float4 q, float4& res) {
    int off = g_off[r * NN + node];
    int dg  = g_deg[r * NN + node];
    float4 acc = make_float4(0.f, 0.f, 0.f, 0.f);
    float z = 0.f;
    int e = 0;
    for (; e + 2 <= dg; e += 2) {
        int s0 = g_csr[off + e];
        int s1 = g_csr[off + e + 1];
        const float4* kv0 = reinterpret_cast<const float4*>(kvbuf + (size_t)s0 * 256);
        const float4* kv1 = reinterpret_cast<const float4*>(kvbuf + (size_t)s1 * 256);
        float4 kp0 = kv0[lane];
        float4 kp1 = kv1[lane];
        float4 vp0 = kv0[32 + lane];
        float4 vp1 = kv1[32 + lane];
        float p0 = q.x * kp0.x + q.y * kp0.y + q.z * kp0.z + q.w * kp0.w;
        float p1 = q.x * kp1.x + q.y * kp1.y + q.z * kp1.z + q.w * kp1.w;
        p0 += __shfl_xor_sync(0xffffffffu, p0, 1);
        p1 += __shfl_xor_sync(0xffffffffu, p1, 1);
        p0 += __shfl_xor_sync(0xffffffffu, p0, 2);
        p1 += __shfl_xor_sync(0xffffffffu, p1, 2);
        float e0 = expf(p0), e1 = expf(p1);
        z += e0 + e1;
        acc.x += e0 * vp0.x + e1 * vp1.x;
        acc.y += e0 * vp0.y + e1 * vp1.y;
        acc.z += e0 * vp0.z + e1 * vp1.z;
        acc.w += e0 * vp0.w + e1 * vp1.w;
    }
    if (e < dg) {
        int s = g_csr[off + e];
        const float4* kv = reinterpret_cast<const float4*>(kvbuf + (size_t)s * 256);
        float4 kp = kv[lane];
        float4 vp = kv[32 + lane];
        float p = q.x * kp.x + q.y * kp.y + q.z * kp.z + q.w * kp.w;
        p += __shfl_xor_sync(0xffffffffu, p, 1);
        p += __shfl_xor_sync(0xffffffffu, p, 2);
        float eh = expf(p);
        z += eh;
        acc.x += eh * vp.x; acc.y += eh * vp.y;
        acc.z += eh * vp.z; acc.w += eh * vp.w;
    }
    if (z > 0.f) {
        float inv = 1.f / z;
        res.x += acc.x * inv; res.y += acc.y * inv;
        res.z += acc.z * inv; res.w += acc.w * inv;
    }
}

__device__ __forceinline__ void write_aimg4(char* img, int node, int lane, float4 v) {
    // cols lane*4..lane*4+3 ; kchunk = lane>>3 ; in-chunk col = (lane&7)*4
    size_t tb = ((size_t)(node >> 7) * 4 + (lane >> 3)) * A_TILE;
    uint32_t byte = (uint32_t)((node & 127) * AROW + (lane & 7) * 4) * 2;
    uint32_t h0, l0, h1, l1;
    split2(v.x, v.y, h0, l0);
    split2(v.z, v.w, h1, l1);
    *reinterpret_cast<uint2*>(img + tb + byte) = make_uint2(h0, h1);
    *reinterpret_cast<uint2*>(img + tb + A_PLANE + byte) = make_uint2(l0, l1);
}

__global__ void agg_type_b() {   // relation 0: a -> b
    int w = (blockIdx.x * blockDim.x + threadIdx.x) >> 5;
    if (w >= NN) return;
    int lane = threadIdx.x & 31;
    float4 q = *reinterpret_cast<const float4*>(g_qb + (size_t)w * 128 + lane * 4);
    float4 res = make_float4(0.f, 0.f, 0.f, 0.f);
    rel_accum(w, lane, 0, g_kv[0], q, res);
    res.x = fmaxf(res.x, 0.f); res.y = fmaxf(res.y, 0.f);
    res.z = fmaxf(res.z, 0.f); res.w = fmaxf(res.w, 0.f);
    write_aimg4(g_it[1], w, lane, res);
}

__global__ void agg_type_a() {   // relations 1 (b->a) + 2 (a->a)
    int w = (blockIdx.x * blockDim.x + threadIdx.x) >> 5;
    if (w >= NN) return;
    int lane = threadIdx.x & 31;
    float4 q = *reinterpret_cast<const float4*>(g_qa + (size_t)w * 128 + lane * 4);
    float4 res = make_float4(0.f, 0.f, 0.f, 0.f);
    rel_accum(w, lane, 1, g_kv[1], q, res);
    rel_accum(w, lane, 2, g_kv[2], q, res);
    res.x = fmaxf(res.x, 0.f); res.y = fmaxf(res.y, 0.f);
    res.z = fmaxf(res.z, 0.f); res.w = fmaxf(res.w, 0.f);
    write_aimg4(g_it[0], w, lane, res);
}

// ---------------------------------------------------------------------------
// LayerNorm: reads fp32 g_x, writes A-image
// ---------------------------------------------------------------------------
__global__ void layernorm(const float* __restrict__ X, const float* __restrict__ gamma,
                          const float* __restrict__ beta, char* __restrict__ img) {
    int w = (blockIdx.x * blockDim.x + threadIdx.x) >> 5;
    if (w >= NN) return;
    int lane = threadIdx.x & 31;
    float4 v = *reinterpret_cast<const float4*>(X + (size_t)w * 128 + lane * 4);
    float s  = v.x + v.y + v.z + v.w;
    float s2 = v.x * v.x + v.y * v.y + v.z * v.z + v.w * v.w;
#pragma unroll
    for (int ofs = 16; ofs > 0; ofs >>= 1) {
        s  += __shfl_xor_sync(0xffffffffu, s, ofs);
        s2 += __shfl_xor_sync(0xffffffffu, s2, ofs);
    }
    float mu   = s * (1.f / 128.f);
    float var  = s2 * (1.f / 128.f) - mu * mu;
    float rstd = rsqrtf(var + 1e-5f);
    float4 g = *reinterpret_cast<const float4*>(gamma + lane * 4);
    float4 b = *reinterpret_cast<const float4*>(beta + lane * 4);
    float4 o;
    o.x = (v.x - mu) * rstd * g.x + b.x;
    o.y = (v.y - mu) * rstd * g.y + b.y;
    o.z = (v.z - mu) * rstd * g.z + b.z;
    o.w = (v.w - mu) * rstd * g.w + b.w;
    write_aimg4(img, w, lane, o);
}

// ---------------------------------------------------------------------------
// Launch
// ---------------------------------------------------------------------------
extern "C" void kernel_launch(void* const* d_in, const int* in_sizes, int n_in,
                              void* d_out, int out_size) {
    const float* h_a   = (const float*)d_in[0];
    const float* h_b   = (const float*)d_in[1];
    const float* Wk    = (const float*)d_in[2];
    const float* bk    = (const float*)d_in[3];
    const float* Wq    = (const float*)d_in[4];
    const float* bq    = (const float*)d_in[5];
    const float* Wv    = (const float*)d_in[6];
    const float* bv    = (const float*)d_in[7];
    const float* Wa    = (const float*)d_in[8];
    const float* ba    = (const float*)d_in[9];
    const float* gamma = (const float*)d_in[10];
    const float* beta  = (const float*)d_in[11];
    const float* W1    = (const float*)d_in[12];
    const float* b1    = (const float*)d_in[13];
    const float* W2    = (const float*)d_in[14];
    const float* b2    = (const float*)d_in[15];
    const float* pri   = (const float*)d_in[16];
    const float* att   = (const float*)d_in[17];
    const float* msg   = (const float*)d_in[18];
    const void* src0 = d_in[19]; const void* dst0 = d_in[20];
    const void* src1 = d_in[21]; const void* dst1 = d_in[22];
    const void* src2 = d_in[23]; const void* dst2 = d_in[24];
    float* out = (float*)d_out;

    float *p_qa, *p_qb, *p_kv, *p_x, *p_Wkv, *p_bkv;
    char *p_wimg, *p_ia, *p_ib, *p_it, *p_ix, *p_iff;
    cudaGetSymbolAddress((void**)&p_qa,   g_qa);
    cudaGetSymbolAddress((void**)&p_qb,   g_qb);
    cudaGetSymbolAddress((void**)&p_kv,   g_kv);
    cudaGetSymbolAddress((void**)&p_x,    g_x);
    cudaGetSymbolAddress((void**)&p_Wkv,  g_Wkv);
    cudaGetSymbolAddress((void**)&p_bkv,  g_bkv);
    cudaGetSymbolAddress((void**)&p_wimg, g_wimg);
    cudaGetSymbolAddress((void**)&p_ia,   g_ia);
    cudaGetSymbolAddress((void**)&p_ib,   g_ib);
    cudaGetSymbolAddress((void**)&p_it,   g_it);
    cudaGetSymbolAddress((void**)&p_ix,   g_ix);
    cudaGetSymbolAddress((void**)&p_iff,  g_iff);

    cudaFuncSetAttribute(tgemm6<false,false,false>, cudaFuncAttributeMaxDynamicSharedMemorySize, TG_SMEM);
    cudaFuncSetAttribute(tgemm6<true,false,false>,  cudaFuncAttributeMaxDynamicSharedMemorySize, TG_SMEM);
    cudaFuncSetAttribute(tgemm6<false,true,true>,   cudaFuncAttributeMaxDynamicSharedMemorySize, TG_SMEM);

    const int gy = RB;                          // 782
    const int eb = (EE + 255) / 256;
    const int wb = (NN * 32) / 256;
    const int ib128 = (NN * 64 + 255) / 256;    // M*K/2 threads for prep_img_a (K=128)

    // 0. reset + edge dtype detection
    zero_deg<<<(NSCAN + 255) / 256, 256>>>();
    detect_i32<<<(EE / 2 + 255) / 256, 256>>>((const int*)dst0);

    // 1. weights + images
    prep_weights<<<(6 * CIN * COUT + 255) / 256, 256>>>(Wk, bk, Wv, bv, pri, att, msg);
    prep_img_w<<<64, 256>>>(Wq,              p_wimg + WQ0, 128, 128);
    prep_img_w<<<64, 256>>>(Wq + 16384,      p_wimg + WQ1, 128, 128);
    prep_img_w<<<128, 256>>>(p_Wkv,           p_wimg + WKV0, 128, 256);
    prep_img_w<<<128, 256>>>(p_Wkv + 32768,   p_wimg + WKV1, 128, 256);
    prep_img_w<<<128, 256>>>(p_Wkv + 65536,   p_wimg + WKV2, 128, 256);
    prep_img_w<<<64, 256>>>(Wa,              p_wimg + WA0, 128, 128);
    prep_img_w<<<64, 256>>>(Wa + 16384,      p_wimg + WA1, 128, 128);
    prep_img_w<<<256, 256>>>(W1,              p_wimg + W10, 128, 512);
    prep_img_w<<<256, 256>>>(W1 + 65536,      p_wimg + W11, 128, 512);
    prep_img_w<<<256, 256>>>(W2,              p_wimg + W20, 512, 128);
    prep_img_w<<<256, 256>>>(W2 + 65536,      p_wimg + W21, 512, 128);
    prep_img_a<<<ib128, 256>>>(h_a, p_ia, NN, 128);
    prep_img_a<<<ib128, 256>>>(h_b, p_ib, NN, 128);

    // 2. projections
    tgemm6<false,false,false><<<dim3(1, gy), 256, TG_SMEM>>>(p_ia, p_wimg + WQ0,  bq,       nullptr, p_qa, nullptr, NN, 128, 128);
    tgemm6<false,false,false><<<dim3(1, gy), 256, TG_SMEM>>>(p_ib, p_wimg + WQ1,  bq + 128, nullptr, p_qb, nullptr, NN, 128, 128);
    tgemm6<false,false,false><<<dim3(2, gy), 256, TG_SMEM>>>(p_ia, p_wimg + WKV0, p_bkv,       nullptr, p_kv,                          nullptr, NN, 256, 128);
    tgemm6<false,false,false><<<dim3(2, gy), 256, TG_SMEM>>>(p_ib, p_wimg + WKV1, p_bkv + 256, nullptr, p_kv + (size_t)NN * 256,       nullptr, NN, 256, 128);
    tgemm6<false,false,false><<<dim3(2, gy), 256, TG_SMEM>>>(p_ia, p_wimg + WKV2, p_bkv + 512, nullptr, p_kv + 2 * (size_t)NN * 256,   nullptr, NN, 256, 128);

    // 3. CSR build
    count_deg<<<eb, 256>>>(dst0, 0);
    count_deg<<<eb, 256>>>(dst1, 1);
    count_deg<<<eb, 256>>>(dst2, 2);
    scan1<<<SCAN_NB, SCAN_BS>>>();
    scan2<<<1, 512>>>();
    scan3<<<SCAN_NB, SCAN_BS>>>();
    scatter_edges<<<eb, 256>>>(src0, dst0, 0);
    scatter_edges<<<eb, 256>>>(src1, dst1, 1);
    scatter_edges<<<eb, 256>>>(src2, dst2, 2);

    // 4. attention aggregation -> relu(t) images
    agg_type_b<<<wb, 256>>>();
    agg_type_a<<<wb, 256>>>();

    // 5. per-type update
    for (int t = 0; t < 2; t++) {
        const float* hres = t ? h_b : h_a;
        tgemm6<true,false,false><<<dim3(1, gy), 256, TG_SMEM>>>(
            p_it + (size_t)t * AIMG_K128, p_wimg + (t ? WA1 : WA0),
            ba + t * 128, hres, p_x, nullptr, NN, 128, 128);
        layernorm<<<wb, 256>>>(p_x, gamma + t * 128, beta + t * 128, p_ix);
        tgemm6<false,true,true><<<dim3(4, gy), 256, TG_SMEM>>>(
            p_ix, p_wimg + (t ? W11 : W10),
            b1 + t * 512, nullptr, nullptr, p_iff, NN, 512, 128);
        tgemm6<false,false,false><<<dim3(1, gy), 256, TG_SMEM>>>(
            p_iff, p_wimg + (t ? W21 : W20),
            b2 + t * 128, nullptr, out + (size_t)t * NN * 128, nullptr, NN, 128, 512);
    }
}

// round 12
// speedup vs baseline: 1.4483x; 1.1329x over previous
#include <cuda_runtime.h>
#include <cuda_fp16.h>
#include <math.h>
#include <stdint.h>

// ---------------------------------------------------------------------------
// Problem constants
// ---------------------------------------------------------------------------
namespace {
constexpr int NN   = 100000;
constexpr int EE   = 500000;
constexpr int CIN  = 128;
constexpr int COUT = 128;
constexpr int NH   = 8;
constexpr int DKH  = 16;
constexpr int DFF  = 512;
constexpr int NSCAN   = 3 * NN;
constexpr int SCAN_BS = 1024;
constexpr int SCAN_NB = (NSCAN + SCAN_BS - 1) / SCAN_BS;  // 293

// GEMM tile geometry. A = fp16 hi/lo planes (exact split); B = single fp16.
constexpr int AROW = 40;    // A smem row stride (fp16) - conflict-free ldmatrix
constexpr int BROW = 136;   // B smem row stride (fp16) - conflict-free ldmatrix
constexpr int A_PLANE = 128 * AROW * 2;       // 10240 B
constexpr int A_TILE  = 2 * A_PLANE;          // 20480 B
constexpr int B_TILE  = 32 * BROW * 2;        // 8704 B (single plane)
constexpr int BUF_BYTES = A_TILE + B_TILE;    // 29184
constexpr int TG_SMEM = 2 * BUF_BYTES;        // 58368 (double buffered)
constexpr int RB = 782;

// weight image offsets (bytes); per-colblock block = ntilesK * B_TILE
constexpr size_t WQ0 = 0,        WQ1 = 34816;
constexpr size_t WA0 = 69632,    WA1 = 104448;
constexpr size_t WKV0 = 139264,  WKV1 = 208896, WKV2 = 278528;
constexpr size_t W10 = 348160,   W11 = 487424;
constexpr size_t W20 = 626688,   W21 = 765952;
constexpr size_t WIMG_TOTAL = 905216;

constexpr size_t AIMG_K128 = (size_t)RB * 4 * A_TILE;
constexpr size_t AIMG_K512 = (size_t)RB * 16 * A_TILE;
}

// ---------------------------------------------------------------------------
// Device scratch
// ---------------------------------------------------------------------------
__device__ float g_qa[(size_t)NN * COUT];
__device__ float g_qb[(size_t)NN * COUT];
__device__ float g_kv[3][(size_t)NN * 2 * COUT];
__device__ float g_x[(size_t)NN * COUT];
__device__ float g_Wkv[3][CIN * 2 * COUT];
__device__ float g_bkv[3][2 * COUT];
__device__ __align__(16) char g_wimg[WIMG_TOTAL];
__device__ __align__(16) char g_ia[AIMG_K128];
__device__ __align__(16) char g_ib[AIMG_K128];
__device__ __align__(16) char g_it[2][AIMG_K128];
__device__ __align__(16) char g_ix[AIMG_K128];
__device__ __align__(16) char g_iff[AIMG_K512];
__device__ int   g_deg[NSCAN];
__device__ int   g_off[NSCAN];
__device__ int   g_wpos[NSCAN];
__device__ int   g_csr[3 * EE];
__device__ int   g_part[512];
__device__ int   g_part_scan[512];
__device__ int   g_i32;

// ---------------------------------------------------------------------------
// helpers
// ---------------------------------------------------------------------------
__device__ __forceinline__ void mma16(float* c, const uint32_t* a, const uint32_t* b) {
    asm volatile(
        "mma.sync.aligned.m16n8k16.row.col.f32.f16.f16.f32 "
        "{%0,%1,%2,%3}, {%4,%5,%6,%7}, {%8,%9}, {%0,%1,%2,%3};"
        : "+f"(c[0]), "+f"(c[1]), "+f"(c[2]), "+f"(c[3])
        : "r"(a[0]), "r"(a[1]), "r"(a[2]), "r"(a[3]), "r"(b[0]), "r"(b[1]));
}
__device__ __forceinline__ void ldmx4(uint32_t* r, uint32_t saddr) {
    asm volatile("ldmatrix.sync.aligned.m8n8.x4.shared.b16 {%0,%1,%2,%3}, [%4];"
                 : "=r"(r[0]), "=r"(r[1]), "=r"(r[2]), "=r"(r[3]) : "r"(saddr));
}
__device__ __forceinline__ void ldmx4t(uint32_t* r, uint32_t saddr) {
    asm volatile("ldmatrix.sync.aligned.m8n8.x4.trans.shared.b16 {%0,%1,%2,%3}, [%4];"
                 : "=r"(r[0]), "=r"(r[1]), "=r"(r[2]), "=r"(r[3]) : "r"(saddr));
}
__device__ __forceinline__ void cpa16(uint32_t smem, const char* g) {
    asm volatile("cp.async.cg.shared.global [%0], [%1], 16;" :: "r"(smem), "l"(g));
}
#define CPA_COMMIT() asm volatile("cp.async.commit_group;" ::: "memory")
#define CPA_WAIT0()  asm volatile("cp.async.wait_group 0;" ::: "memory")
#define CPA_WAIT1()  asm volatile("cp.async.wait_group 1;" ::: "memory")

// fp16 exact split of a pair: hi = h16(x), lo = h16(x - hi)  (lo exact to fp32)
__device__ __forceinline__ void split2h(float a, float b, uint32_t& hi, uint32_t& lo) {
    __half2 h = __floats2half2_rn(a, b);
    __half2 l = __floats2half2_rn(a - __low2float(h), b - __high2float(h));
    hi = *reinterpret_cast<uint32_t*>(&h);
    lo = *reinterpret_cast<uint32_t*>(&l);
}

// ---------------------------------------------------------------------------
// Fused per-relation weight prep (fp32)
// ---------------------------------------------------------------------------
__global__ void prep_weights(const float* __restrict__ Wk, const float* __restrict__ bk,
                             const float* __restrict__ Wv, const float* __restrict__ bv,
                             const float* __restrict__ pri, const float* __restrict__ att,
                             const float* __restrict__ msg) {
    int idx = blockIdx.x * blockDim.x + threadIdx.x;
    if (idx >= 6 * CIN * COUT) return;
    int combo = idx >> 14;
    int rem   = idx & 16383;
    int i = rem >> 7;
    int j = rem & 127;
    int r = combo >> 1;
    int kind = combo & 1;
    int t = (r == 1) ? 1 : 0;
    const float* Ws = (kind ? Wv : Wk) + (size_t)t * CIN * COUT;
    const float* bs = (kind ? bv : bk) + t * COUT;
    const float* Rm = (kind ? msg : att) + (size_t)r * NH * DKH * DKH;
    int h = j >> 4, jj = j & 15;
    float scale = kind ? 1.0f : pri[r * NH + h] * 0.25f;
    float s = 0.f;
#pragma unroll
    for (int d = 0; d < DKH; d++)
        s += Ws[(size_t)i * COUT + h * DKH + d] * Rm[h * DKH * DKH + d * DKH + jj];
    g_Wkv[r][i * 256 + kind * 128 + j] = s * scale;
    if (i == 0) {
        float b = 0.f;
#pragma unroll
        for (int d = 0; d < DKH; d++)
            b += bs[h * DKH + d] * Rm[h * DKH * DKH + d * DKH + jj];
        g_bkv[r][kind * 128 + j] = b * scale;
    }
}

// ---------------------------------------------------------------------------
// Weight image builder (single fp16 plane), all 11 images in one launch.
// ---------------------------------------------------------------------------
__device__ __forceinline__ void put_w(const float* src, size_t dimg, int K, int N, int li) {
    int k = li / N, n = li % N;
    float v = src[li];
    size_t tb = dimg + ((size_t)(n >> 7) * (K >> 5) + (k >> 5)) * B_TILE;
    uint32_t byte = (uint32_t)((k & 31) * BROW + (n & 127)) * 2;
    *reinterpret_cast<__half*>(g_wimg + tb + byte) = __float2half(v);
}

__global__ void prep_img_w_all(const float* __restrict__ Wq, const float* __restrict__ Wa,
                               const float* __restrict__ W1, const float* __restrict__ W2) {
    int idx = blockIdx.x * blockDim.x + threadIdx.x;
    if (idx < 65536) {                       // Wq0,Wq1,Wa0,Wa1 (16384 each)
        int s = idx >> 14, li = idx & 16383;
        const float* src = (s < 2) ? (Wq + s * 16384) : (Wa + (s - 2) * 16384);
        size_t dst = (s == 0) ? WQ0 : (s == 1) ? WQ1 : (s == 2) ? WA0 : WA1;
        put_w(src, dst, 128, 128, li);
    } else if (idx < 163840) {               // Wkv r (32768 each)
        int rel = idx - 65536;
        int s = rel >> 15, li = rel & 32767;
        size_t dst = (s == 0) ? WKV0 : (s == 1) ? WKV1 : WKV2;
        put_w(g_Wkv[s], dst, 128, 256, li);
    } else if (idx < 425984) {               // W1t0,W1t1,W2t0,W2t1 (65536 each)
        int rel = idx - 163840;
        int s = rel >> 16, li = rel & 65535;
        if (s < 2) put_w(W1 + s * 65536, s ? W11 : W10, 128, 512, li);
        else       put_w(W2 + (s - 2) * 65536, (s - 2) ? W21 : W20, 512, 128, li);
    }
}

// ---------------------------------------------------------------------------
// Activation image builder (fp16 hi/lo planes), h_a + h_b in one launch
// ---------------------------------------------------------------------------
__global__ void prep_img_a_all(const float* __restrict__ Xa, const float* __restrict__ Xb) {
    int idx = blockIdx.x * blockDim.x + threadIdx.x;
    if (idx >= 2 * NN * 64) return;
    const float* X = (idx < NN * 64) ? Xa : Xb;
    char* img = (idx < NN * 64) ? g_ia : g_ib;
    int li = (idx < NN * 64) ? idx : idx - NN * 64;
    int m = li >> 6, kp = (li & 63) * 2;
    float2 v = *reinterpret_cast<const float2*>(X + (size_t)m * 128 + kp);
    uint32_t hi, lo;
    split2h(v.x, v.y, hi, lo);
    size_t tb = ((size_t)(m >> 7) * 4 + (kp >> 5)) * A_TILE;
    uint32_t byte = (uint32_t)((m & 127) * AROW + (kp & 31)) * 2;
    *reinterpret_cast<uint32_t*>(img + tb + byte) = hi;
    *reinterpret_cast<uint32_t*>(img + tb + A_PLANE + byte) = lo;
}

// ---------------------------------------------------------------------------
// fp16 2-term GEMM: C = (Ah+Al)@Bh (+bias)(+Res)(relu?) ; cp.async staging,
// double-buffered; inner loop pure ldmatrix + mma. OUT_IMG: write A-image.
// ---------------------------------------------------------------------------
template<bool RES, bool RELU_OUT, bool OUT_IMG>
__global__ __launch_bounds__(256, 2) void tgemm6(
        const char* __restrict__ AImg, const char* __restrict__ BImg,
        const float* __restrict__ bias, const float* __restrict__ Rp,
        float* __restrict__ C, char* __restrict__ OutImg,
        int M, int Ncols, int K) {
    extern __shared__ __align__(16) char dsm[];
    const uint32_t sm0 = (uint32_t)__cvta_generic_to_shared(dsm);

    const int tid = threadIdx.x;
    const int wid = tid >> 5, lane = tid & 31;
    const int wm = wid & 3, wn = wid >> 2;
    const int wrow = wm * 32, wcol = wn * 64;
    const int row0 = blockIdx.y * 128;
    const int col0 = blockIdx.x * 128;
    const int ntiles = K >> 5;

    float acc[2][8][4];
#pragma unroll
    for (int mt = 0; mt < 2; mt++)
#pragma unroll
        for (int nt = 0; nt < 8; nt++)
#pragma unroll
            for (int r = 0; r < 4; r++) acc[mt][nt][r] = 0.f;

    const int lrow = (lane & 7) + ((lane >> 3) & 1) * 8;
    const int lcol = (lane >> 4) * 8;

    const char* abase = AImg + (size_t)blockIdx.y * ntiles * A_TILE;
    const char* bbase = BImg + (size_t)blockIdx.x * ntiles * B_TILE;

    // issue tile 0 (A 1280 + B 544 = 1824 16B chunks)
    {
        uint32_t dst = sm0;
#pragma unroll
        for (int i = 0; i < 8; i++) {
            int idx = tid + i * 256;
            if (idx < 1280)      cpa16(dst + idx * 16, abase + idx * 16);
            else if (idx < 1824) cpa16(dst + A_TILE + (idx - 1280) * 16, bbase + (idx - 1280) * 16);
        }
        CPA_COMMIT();
    }

    for (int t = 0; t < ntiles; t++) {
        const bool have_next = (t + 1 < ntiles);
        if (have_next) {
            const char* as = abase + (size_t)(t + 1) * A_TILE;
            const char* bs = bbase + (size_t)(t + 1) * B_TILE;
            uint32_t dst = sm0 + ((t + 1) & 1) * BUF_BYTES;
#pragma unroll
            for (int i = 0; i < 8; i++) {
                int idx = tid + i * 256;
                if (idx < 1280)      cpa16(dst + idx * 16, as + idx * 16);
                else if (idx < 1824) cpa16(dst + A_TILE + (idx - 1280) * 16, bs + (idx - 1280) * 16);
            }
            CPA_COMMIT();
            CPA_WAIT1();
        } else {
            CPA_WAIT0();
        }
        __syncthreads();

        const uint32_t cur = sm0 + (t & 1) * BUF_BYTES;
#pragma unroll
        for (int kc = 0; kc < 2; kc++) {
            const int k0 = kc * 16;
            uint32_t ahi[2][4], alo[2][4];
#pragma unroll
            for (int mt = 0; mt < 2; mt++) {
                uint32_t off = (uint32_t)((wrow + mt * 16 + lrow) * AROW + k0 + lcol) * 2;
                ldmx4(ahi[mt], cur + off);
                ldmx4(alo[mt], cur + A_PLANE + off);
            }
#pragma unroll
            for (int ng = 0; ng < 4; ng++) {
                uint32_t bf[4];
                uint32_t off = (uint32_t)((k0 + lrow) * BROW + wcol + ng * 16 + lcol) * 2;
                ldmx4t(bf, cur + A_TILE + off);
#pragma unroll
                for (int mt = 0; mt < 2; mt++) {
                    mma16(acc[mt][2 * ng],     ahi[mt], bf);
                    mma16(acc[mt][2 * ng],     alo[mt], bf);
                    mma16(acc[mt][2 * ng + 1], ahi[mt], bf + 2);
                    mma16(acc[mt][2 * ng + 1], alo[mt], bf + 2);
                }
            }
        }
        __syncthreads();
    }

    // epilogue
    const int okc = Ncols >> 5;
#pragma unroll
    for (int mt = 0; mt < 2; mt++) {
#pragma unroll
        for (int nt = 0; nt < 8; nt++) {
            int gr0 = row0 + wrow + mt * 16 + (lane >> 2);
            int gc  = col0 + wcol + nt * 8 + (lane & 3) * 2;
            float2 bb = *reinterpret_cast<const float2*>(&bias[gc]);
#pragma unroll
            for (int hh = 0; hh < 2; hh++) {
                int r = gr0 + hh * 8;
                if (r >= M) continue;
                float o0 = acc[mt][nt][hh * 2 + 0] + bb.x;
                float o1 = acc[mt][nt][hh * 2 + 1] + bb.y;
                if (RES) {
                    float2 rr = *reinterpret_cast<const float2*>(Rp + (size_t)r * Ncols + gc);
                    o0 += rr.x; o1 += rr.y;
                }
                if (RELU_OUT) { o0 = fmaxf(o0, 0.f); o1 = fmaxf(o1, 0.f); }
                if (OUT_IMG) {
                    uint32_t hi, lo;
                    split2h(o0, o1, hi, lo);
                    size_t tb = ((size_t)(r >> 7) * okc + (gc >> 5)) * A_TILE;
                    uint32_t byte = (uint32_t)((r & 127) * AROW + (gc & 31)) * 2;
                    *reinterpret_cast<uint32_t*>(OutImg + tb + byte) = hi;
                    *reinterpret_cast<uint32_t*>(OutImg + tb + A_PLANE + byte) = lo;
                } else {
                    *reinterpret_cast<float2*>(C + (size_t)r * Ncols + gc) = make_float2(o0, o1);
                }
            }
        }
    }
}

// ---------------------------------------------------------------------------
// Edge-index helpers
// ---------------------------------------------------------------------------
__global__ void zero_deg() {
    int i = blockIdx.x * blockDim.x + threadIdx.x;
    if (i == 0) g_i32 = 0;
    if (i < NSCAN) g_deg[i] = 0;
}
__global__ void detect_i32(const int* __restrict__ d) {
    int i = blockIdx.x * blockDim.x + threadIdx.x;
    if (i >= EE / 2) return;
    if (d[2 * i + 1] != 0) g_i32 = 1;
}
__device__ __forceinline__ int eidx(const void* p, int i, int is32) {
    return is32 ? ((const int*)p)[i] : (int)((const long long*)p)[i];
}
__global__ void count_deg(const void* __restrict__ dst, int r) {
    int i = blockIdx.x * blockDim.x + threadIdx.x;
    if (i >= EE) return;
    int is32 = g_i32;
    atomicAdd(&g_deg[r * NN + eidx(dst, i, is32)], 1);
}
__global__ void scatter_edges(const void* __restrict__ src, const void* __restrict__ dst, int r) {
    int i = blockIdx.x * blockDim.x + threadIdx.x;
    if (i >= EE) return;
    int is32 = g_i32;
    int d = eidx(dst, i, is32);
    int p = atomicAdd(&g_wpos[r * NN + d], 1);
    g_csr[p] = eidx(src, i, is32);
}

// ---------------------------------------------------------------------------
// Exclusive scan over g_deg[3N]
// ---------------------------------------------------------------------------
__global__ void scan1() {
    __shared__ int sh[SCAN_BS];
    int i = blockIdx.x * SCAN_BS + threadIdx.x;
    sh[threadIdx.x] = (i < NSCAN) ? g_deg[i] : 0;
    __syncthreads();
    for (int ofs = SCAN_BS / 2; ofs > 0; ofs >>= 1) {
        if (threadIdx.x < ofs) sh[threadIdx.x] += sh[threadIdx.x + ofs];
        __syncthreads();
    }
    if (threadIdx.x == 0) g_part[blockIdx.x] = sh[0];
}
__global__ void scan2() {
    __shared__ int a[512], b[512];
    int t = threadIdx.x;
    int v = (t < SCAN_NB) ? g_part[t] : 0;
    a[t] = v; __syncthreads();
    int* s = a; int* d = b;
    for (int ofs = 1; ofs < 512; ofs <<= 1) {
        int x = s[t];
        if (t >= ofs) x += s[t - ofs];
        d[t] = x; __syncthreads();
        int* tmp = s; s = d; d = tmp;
    }
    g_part_scan[t] = s[t] - v;
}
__global__ void scan3() {
    __shared__ int a[SCAN_BS], b[SCAN_BS];
    int t = threadIdx.x;
    int i = blockIdx.x * SCAN_BS + t;
    int v = (i < NSCAN) ? g_deg[i] : 0;
    a[t] = v; __syncthreads();
    int* s = a; int* d = b;
    for (int ofs = 1; ofs < SCAN_BS; ofs <<= 1) {
        int x = s[t];
        if (t >= ofs) x += s[t - ofs];
        d[t] = x; __syncthreads();
        int* tmp = s; s = d; d = tmp;
    }
    if (i < NSCAN) {
        int excl = s[t] - v + g_part_scan[blockIdx.x];
        g_off[i]  = excl;
        g_wpos[i] = excl;
    }
}

// ---------------------------------------------------------------------------
// Attention aggregation -> writes relu(t) A-image directly
// ---------------------------------------------------------------------------
__device__ __forceinline__ void rel_accum(int node, int lane, int r,
                                          const float* __restrict__ kvbuf,
                                          float4 q, float4& res) {
    int off = g_off[r * NN + node];
    int dg  = g_deg[r * NN + node];
    float4 acc = make_float4(0.f, 0.f, 0.f, 0.f);
    float z = 0.f;
    int e = 0;
    for (; e + 2 <= dg; e += 2) {
        int s0 = g_csr[off + e];
        int s1 = g_csr[off + e + 1];
        const float4* kv0 = reinterpret_cast<const float4*>(kvbuf + (size_t)s0 * 256);
        const float4* kv1 = reinterpret_cast<const float4*>(kvbuf + (size_t)s1 * 256);
        float4 kp0 = kv0[lane];
        float4 kp1 = kv1[lane];
        float4 vp0 = kv0[32 + lane];
        float4 vp1 = kv1[32 + lane];
        float p0 = q.x * kp0.x + q.y * kp0.y + q.z * kp0.z + q.w * kp0.w;
        float p1 = q.x * kp1.x + q.y * kp1.y + q.z * kp1.z + q.w * kp1.w;
        p0 += __shfl_xor_sync(0xffffffffu, p0, 1);
        p1 += __shfl_xor_sync(0xffffffffu, p1, 1);
        p0 += __shfl_xor_sync(0xffffffffu, p0, 2);
        p1 += __shfl_xor_sync(0xffffffffu, p1, 2);
        float e0 = expf(p0), e1 = expf(p1);
        z += e0 + e1;
        acc.x += e0 * vp0.x + e1 * vp1.x;
        acc.y += e0 * vp0.y + e1 * vp1.y;
        acc.z += e0 * vp0.z + e1 * vp1.z;
        acc.w += e0 * vp0.w + e1 * vp1.w;
    }
    if (e < dg) {
        int s = g_csr[off + e];
        const float4* kv = reinterpret_cast<const float4*>(kvbuf + (size_t)s * 256);
        float4 kp = kv[lane];
        float4 vp = kv[32 + lane];
        float p = q.x * kp.x + q.y * kp.y + q.z * kp.z + q.w * kp.w;
        p += __shfl_xor_sync(0xffffffffu, p, 1);
        p += __shfl_xor_sync(0xffffffffu, p, 2);
        float eh = expf(p);
        z += eh;
        acc.x += eh * vp.x; acc.y += eh * vp.y;
        acc.z += eh * vp.z; acc.w += eh * vp.w;
    }
    if (z > 0.f) {
        float inv = 1.f / z;
        res.x += acc.x * inv; res.y += acc.y * inv;
        res.z += acc.z * inv; res.w += acc.w * inv;
    }
}

__device__ __forceinline__ void write_aimg4(char* img, int node, int lane, float4 v) {
    size_t tb = ((size_t)(node >> 7) * 4 + (lane >> 3)) * A_TILE;
    uint32_t byte = (uint32_t)((node & 127) * AROW + (lane & 7) * 4) * 2;
    uint32_t h0, l0, h1, l1;
    split2h(v.x, v.y, h0, l0);
    split2h(v.z, v.w, h1, l1);
    *reinterpret_cast<uint2*>(img + tb + byte) = make_uint2(h0, h1);
    *reinterpret_cast<uint2*>(img + tb + A_PLANE + byte) = make_uint2(l0, l1);
}

__global__ void agg_type_b() {
    int w = (blockIdx.x * blockDim.x + threadIdx.x) >> 5;
    if (w >= NN) return;
    int lane = threadIdx.x & 31;
    float4 q = *reinterpret_cast<const float4*>(g_qb + (size_t)w * 128 + lane * 4);
    float4 res = make_float4(0.f, 0.f, 0.f, 0.f);
    rel_accum(w, lane, 0, g_kv[0], q, res);
    res.x = fmaxf(res.x, 0.f); res.y = fmaxf(res.y, 0.f);
    res.z = fmaxf(res.z, 0.f); res.w = fmaxf(res.w, 0.f);
    write_aimg4(g_it[1], w, lane, res);
}

__global__ void agg_type_a() {
    int w = (blockIdx.x * blockDim.x + threadIdx.x) >> 5;
    if (w >= NN) return;
    int lane = threadIdx.x & 31;
    float4 q = *reinterpret_cast<const float4*>(g_qa + (size_t)w * 128 + lane * 4);
    float4 res = make_float4(0.f, 0.f, 0.f, 0.f);
    rel_accum(w, lane, 1, g_kv[1], q, res);
    rel_accum(w, lane, 2, g_kv[2], q, res);
    res.x = fmaxf(res.x, 0.f); res.y = fmaxf(res.y, 0.f);
    res.z = fmaxf(res.z, 0.f); res.w = fmaxf(res.w, 0.f);
    write_aimg4(g_it[0], w, lane, res);
}

// ---------------------------------------------------------------------------
// LayerNorm: reads fp32 g_x, writes A-image
// ---------------------------------------------------------------------------
__global__ void layernorm(const float* __restrict__ X, const float* __restrict__ gamma,
                          const float* __restrict__ beta, char* __restrict__ img) {
    int w = (blockIdx.x * blockDim.x + threadIdx.x) >> 5;
    if (w >= NN) return;
    int lane = threadIdx.x & 31;
    float4 v = *reinterpret_cast<const float4*>(X + (size_t)w * 128 + lane * 4);
    float s  = v.x + v.y + v.z + v.w;
    float s2 = v.x * v.x + v.y * v.y + v.z * v.z + v.w * v.w;
#pragma unroll
    for (int ofs = 16; ofs > 0; ofs >>= 1) {
        s  += __shfl_xor_sync(0xffffffffu, s, ofs);
        s2 += __shfl_xor_sync(0xffffffffu, s2, ofs);
    }
    float mu   = s * (1.f / 128.f);
    float var  = s2 * (1.f / 128.f) - mu * mu;
    float rstd = rsqrtf(var + 1e-5f);
    float4 g = *reinterpret_cast<const float4*>(gamma + lane * 4);
    float4 b = *reinterpret_cast<const float4*>(beta + lane * 4);
    float4 o;
    o.x = (v.x - mu) * rstd * g.x + b.x;
    o.y = (v.y - mu) * rstd * g.y + b.y;
    o.z = (v.z - mu) * rstd * g.z + b.z;
    o.w = (v.w - mu) * rstd * g.w + b.w;
    write_aimg4(img, w, lane, o);
}

// ---------------------------------------------------------------------------
// Launch
// ---------------------------------------------------------------------------
extern "C" void kernel_launch(void* const* d_in, const int* in_sizes, int n_in,
                              void* d_out, int out_size) {
    const float* h_a   = (const float*)d_in[0];
    const float* h_b   = (const float*)d_in[1];
    const float* Wk    = (const float*)d_in[2];
    const float* bk    = (const float*)d_in[3];
    const float* Wq    = (const float*)d_in[4];
    const float* bq    = (const float*)d_in[5];
    const float* Wv    = (const float*)d_in[6];
    const float* bv    = (const float*)d_in[7];
    const float* Wa    = (const float*)d_in[8];
    const float* ba    = (const float*)d_in[9];
    const float* gamma = (const float*)d_in[10];
    const float* beta  = (const float*)d_in[11];
    const float* W1    = (const float*)d_in[12];
    const float* b1    = (const float*)d_in[13];
    const float* W2    = (const float*)d_in[14];
    const float* b2    = (const float*)d_in[15];
    const float* pri   = (const float*)d_in[16];
    const float* att   = (const float*)d_in[17];
    const float* msg   = (const float*)d_in[18];
    const void* src0 = d_in[19]; const void* dst0 = d_in[20];
    const void* src1 = d_in[21]; const void* dst1 = d_in[22];
    const void* src2 = d_in[23]; const void* dst2 = d_in[24];
    float* out = (float*)d_out;

    float *p_qa, *p_qb, *p_kv, *p_x, *p_bkv;
    char *p_wimg, *p_ia, *p_ib, *p_it, *p_ix, *p_iff;
    cudaGetSymbolAddress((void**)&p_qa,   g_qa);
    cudaGetSymbolAddress((void**)&p_qb,   g_qb);
    cudaGetSymbolAddress((void**)&p_kv,   g_kv);
    cudaGetSymbolAddress((void**)&p_x,    g_x);
    cudaGetSymbolAddress((void**)&p_bkv,  g_bkv);
    cudaGetSymbolAddress((void**)&p_wimg, g_wimg);
    cudaGetSymbolAddress((void**)&p_ia,   g_ia);
    cudaGetSymbolAddress((void**)&p_ib,   g_ib);
    cudaGetSymbolAddress((void**)&p_it,   g_it);
    cudaGetSymbolAddress((void**)&p_ix,   g_ix);
    cudaGetSymbolAddress((void**)&p_iff,  g_iff);

    cudaFuncSetAttribute(tgemm6<false,false,false>, cudaFuncAttributeMaxDynamicSharedMemorySize, TG_SMEM);
    cudaFuncSetAttribute(tgemm6<true,false,false>,  cudaFuncAttributeMaxDynamicSharedMemorySize, TG_SMEM);
    cudaFuncSetAttribute(tgemm6<false,true,true>,   cudaFuncAttributeMaxDynamicSharedMemorySize, TG_SMEM);

    const int gy = RB;
    const int eb = (EE + 255) / 256;
    const int wb = (NN * 32) / 256;

    // 0. reset + edge dtype detection
    zero_deg<<<(NSCAN + 255) / 256, 256>>>();
    detect_i32<<<(EE / 2 + 255) / 256, 256>>>((const int*)dst0);

    // 1. fused weights + images
    prep_weights<<<(6 * CIN * COUT + 255) / 256, 256>>>(Wk, bk, Wv, bv, pri, att, msg);
    prep_img_w_all<<<(425984 + 255) / 256, 256>>>(Wq, Wa, W1, W2);
    prep_img_a_all<<<(2 * NN * 64 + 255) / 256, 256>>>(h_a, h_b);

    // 2. projections
    tgemm6<false,false,false><<<dim3(1, gy), 256, TG_SMEM>>>(p_ia, p_wimg + WQ0,  bq,       nullptr, p_qa, nullptr, NN, 128, 128);
    tgemm6<false,false,false><<<dim3(1, gy), 256, TG_SMEM>>>(p_ib, p_wimg + WQ1,  bq + 128, nullptr, p_qb, nullptr, NN, 128, 128);
    tgemm6<false,false,false><<<dim3(2, gy), 256, TG_SMEM>>>(p_ia, p_wimg + WKV0, p_bkv,       nullptr, p_kv,                        nullptr, NN, 256, 128);
    tgemm6<false,false,false><<<dim3(2, gy), 256, TG_SMEM>>>(p_ib, p_wimg + WKV1, p_bkv + 256, nullptr, p_kv + (size_t)NN * 256,     nullptr, NN, 256, 128);
    tgemm6<false,false,false><<<dim3(2, gy), 256, TG_SMEM>>>(p_ia, p_wimg + WKV2, p_bkv + 512, nullptr, p_kv + 2 * (size_t)NN * 256, nullptr, NN, 256, 128);

    // 3. CSR build
    count_deg<<<eb, 256>>>(dst0, 0);
    count_deg<<<eb, 256>>>(dst1, 1);
    count_deg<<<eb, 256>>>(dst2, 2);
    scan1<<<SCAN_NB, SCAN_BS>>>();
    scan2<<<1, 512>>>();
    scan3<<<SCAN_NB, SCAN_BS>>>();
    scatter_edges<<<eb, 256>>>(src0, dst0, 0);
    scatter_edges<<<eb, 256>>>(src1, dst1, 1);
    scatter_edges<<<eb, 256>>>(src2, dst2, 2);

    // 4. attention aggregation -> relu(t) images
    agg_type_b<<<wb, 256>>>();
    agg_type_a<<<wb, 256>>>();

    // 5. per-type update
    for (int t = 0; t < 2; t++) {
        const float* hres = t ? h_b : h_a;
        tgemm6<true,false,false><<<dim3(1, gy), 256, TG_SMEM>>>(
            p_it + (size_t)t * AIMG_K128, p_wimg + (t ? WA1 : WA0),
            ba + t * 128, hres, p_x, nullptr, NN, 128, 128);
        layernorm<<<wb, 256>>>(p_x, gamma + t * 128, beta + t * 128, p_ix);
        tgemm6<false,true,true><<<dim3(4, gy), 256, TG_SMEM>>>(
            p_ix, p_wimg + (t ? W11 : W10),
            b1 + t * 512, nullptr, nullptr, p_iff, NN, 512, 128);
        tgemm6<false,false,false><<<dim3(1, gy), 256, TG_SMEM>>>(
            p_iff, p_wimg + (t ? W21 : W20),
            b2 + t * 128, nullptr, out + (size_t)t * NN * 128, nullptr, NN, 128, 512);
    }
}

// round 14
// speedup vs baseline: 1.5252x; 1.0531x over previous
#include <cuda_runtime.h>
#include <cuda_fp16.h>
#include <math.h>
#include <stdint.h>

// ---------------------------------------------------------------------------
// Problem constants
// ---------------------------------------------------------------------------
namespace {
constexpr int NN   = 100000;
constexpr int EE   = 500000;
constexpr int CIN  = 128;
constexpr int COUT = 128;
constexpr int NH   = 8;
constexpr int DKH  = 16;
constexpr int DFF  = 512;
constexpr int NSCAN   = 3 * NN;
constexpr int SCAN_BS = 1024;
constexpr int SCAN_NB = (NSCAN + SCAN_BS - 1) / SCAN_BS;  // 293

// GEMM tile geometry. A = fp16 hi/lo planes (exact split); B = single fp16.
constexpr int AROW = 40;
constexpr int BROW = 136;
constexpr int A_PLANE = 128 * AROW * 2;       // 10240 B
constexpr int A_TILE  = 2 * A_PLANE;          // 20480 B
constexpr int B_TILE  = 32 * BROW * 2;        // 8704 B
constexpr int BUF_BYTES = A_TILE + B_TILE;    // 29184
constexpr int TG_SMEM = 2 * BUF_BYTES;        // 58368
constexpr int RB = 782;

constexpr size_t WQ0 = 0,        WQ1 = 34816;
constexpr size_t WA0 = 69632,    WA1 = 104448;
constexpr size_t WKV0 = 139264,  WKV1 = 208896, WKV2 = 278528;
constexpr size_t W10 = 348160,   W11 = 487424;
constexpr size_t W20 = 626688,   W21 = 765952;
constexpr size_t WIMG_TOTAL = 905216;

constexpr size_t AIMG_K128 = (size_t)RB * 4 * A_TILE;
constexpr size_t AIMG_K512 = (size_t)RB * 16 * A_TILE;
}

// ---------------------------------------------------------------------------
// Device scratch
// ---------------------------------------------------------------------------
__device__ float g_qa[(size_t)NN * COUT];
__device__ float g_qb[(size_t)NN * COUT];
__device__ __half g_kv[3][(size_t)NN * 2 * COUT];   // fp16 kp|vp per relation
__device__ float g_x[(size_t)NN * COUT];
__device__ float g_Wkv[3][CIN * 2 * COUT];
__device__ float g_bkv[3][2 * COUT];
__device__ __align__(16) char g_wimg[WIMG_TOTAL];
__device__ __align__(16) char g_ia[AIMG_K128];
__device__ __align__(16) char g_ib[AIMG_K128];
__device__ __align__(16) char g_it[2][AIMG_K128];
__device__ __align__(16) char g_ix[AIMG_K128];
__device__ __align__(16) char g_iff[AIMG_K512];
__device__ int   g_deg[NSCAN];
__device__ int   g_off[NSCAN];
__device__ int   g_wpos[NSCAN];
__device__ int   g_csr[3 * EE];
__device__ int   g_part[512];
__device__ int   g_part_scan[512];
__device__ int   g_i32;

// ---------------------------------------------------------------------------
// helpers
// ---------------------------------------------------------------------------
__device__ __forceinline__ void mma16(float* c, const uint32_t* a, const uint32_t* b) {
    asm volatile(
        "mma.sync.aligned.m16n8k16.row.col.f32.f16.f16.f32 "
        "{%0,%1,%2,%3}, {%4,%5,%6,%7}, {%8,%9}, {%0,%1,%2,%3};"
        : "+f"(c[0]), "+f"(c[1]), "+f"(c[2]), "+f"(c[3])
        : "r"(a[0]), "r"(a[1]), "r"(a[2]), "r"(a[3]), "r"(b[0]), "r"(b[1]));
}
__device__ __forceinline__ void ldmx4(uint32_t* r, uint32_t saddr) {
    asm volatile("ldmatrix.sync.aligned.m8n8.x4.shared.b16 {%0,%1,%2,%3}, [%4];"
                 : "=r"(r[0]), "=r"(r[1]), "=r"(r[2]), "=r"(r[3]) : "r"(saddr));
}
__device__ __forceinline__ void ldmx4t(uint32_t* r, uint32_t saddr) {
    asm volatile("ldmatrix.sync.aligned.m8n8.x4.trans.shared.b16 {%0,%1,%2,%3}, [%4];"
                 : "=r"(r[0]), "=r"(r[1]), "=r"(r[2]), "=r"(r[3]) : "r"(saddr));
}
__device__ __forceinline__ void cpa16(uint32_t smem, const char* g) {
    asm volatile("cp.async.cg.shared.global [%0], [%1], 16;" :: "r"(smem), "l"(g));
}
#define CPA_COMMIT() asm volatile("cp.async.commit_group;" ::: "memory")
#define CPA_WAIT0()  asm volatile("cp.async.wait_group 0;" ::: "memory")
#define CPA_WAIT1()  asm volatile("cp.async.wait_group 1;" ::: "memory")

__device__ __forceinline__ void split2h(float a, float b, uint32_t& hi, uint32_t& lo) {
    __half2 h = __floats2half2_rn(a, b);
    __half2 l = __floats2half2_rn(a - __low2float(h), b - __high2float(h));
    hi = *reinterpret_cast<uint32_t*>(&h);
    lo = *reinterpret_cast<uint32_t*>(&l);
}

// ---------------------------------------------------------------------------
// Fused per-relation weight prep (fp32)
// ---------------------------------------------------------------------------
__global__ void prep_weights(const float* __restrict__ Wk, const float* __restrict__ bk,
                             const float* __restrict__ Wv, const float* __restrict__ bv,
                             const float* __restrict__ pri, const float* __restrict__ att,
                             const float* __restrict__ msg) {
    int idx = blockIdx.x * blockDim.x + threadIdx.x;
    if (idx >= 6 * CIN * COUT) return;
    int combo = idx >> 14;
    int rem   = idx & 16383;
    int i = rem >> 7;
    int j = rem & 127;
    int r = combo >> 1;
    int kind = combo & 1;
    int t = (r == 1) ? 1 : 0;
    const float* Ws = (kind ? Wv : Wk) + (size_t)t * CIN * COUT;
    const float* bs = (kind ? bv : bk) + t * COUT;
    const float* Rm = (kind ? msg : att) + (size_t)r * NH * DKH * DKH;
    int h = j >> 4, jj = j & 15;
    float scale = kind ? 1.0f : pri[r * NH + h] * 0.25f;
    float s = 0.f;
#pragma unroll
    for (int d = 0; d < DKH; d++)
        s += Ws[(size_t)i * COUT + h * DKH + d] * Rm[h * DKH * DKH + d * DKH + jj];
    g_Wkv[r][i * 256 + kind * 128 + j] = s * scale;
    if (i == 0) {
        float b = 0.f;
#pragma unroll
        for (int d = 0; d < DKH; d++)
            b += bs[h * DKH + d] * Rm[h * DKH * DKH + d * DKH + jj];
        g_bkv[r][kind * 128 + j] = b * scale;
    }
}

// ---------------------------------------------------------------------------
// Weight image builder (single fp16 plane), all 11 images in one launch.
// ---------------------------------------------------------------------------
__device__ __forceinline__ void put_w(const float* src, size_t dimg, int K, int N, int li) {
    int k = li / N, n = li % N;
    float v = src[li];
    size_t tb = dimg + ((size_t)(n >> 7) * (K >> 5) + (k >> 5)) * B_TILE;
    uint32_t byte = (uint32_t)((k & 31) * BROW + (n & 127)) * 2;
    *reinterpret_cast<__half*>(g_wimg + tb + byte) = __float2half(v);
}

__global__ void prep_img_w_all(const float* __restrict__ Wq, const float* __restrict__ Wa,
                               const float* __restrict__ W1, const float* __restrict__ W2) {
    int idx = blockIdx.x * blockDim.x + threadIdx.x;
    if (idx < 65536) {                       // Wq0,Wq1,Wa0,Wa1 (16384 each)
        int s = idx >> 14, li = idx & 16383;
        const float* src = (s < 2) ? (Wq + s * 16384) : (Wa + (s - 2) * 16384);
        size_t dst = (s == 0) ? WQ0 : (s == 1) ? WQ1 : (s == 2) ? WA0 : WA1;
        put_w(src, dst, 128, 128, li);
    } else if (idx < 163840) {               // Wkv r (32768 each)
        int rel = idx - 65536;
        int s = rel >> 15, li = rel & 32767;
        size_t dst = (s == 0) ? WKV0 : (s == 1) ? WKV1 : WKV2;
        put_w(g_Wkv[s], dst, 128, 256, li);
    } else if (idx < 425984) {               // W1t0,W1t1,W2t0,W2t1 (65536 each)
        int rel = idx - 163840;
        int s = rel >> 16, li = rel & 65535;
        if (s < 2) put_w(W1 + s * 65536, s ? W11 : W10, 128, 512, li);
        else       put_w(W2 + (s - 2) * 65536, (s - 2) ? W21 : W20, 512, 128, li);
    }
}

// ---------------------------------------------------------------------------
// Activation image builder (fp16 hi/lo planes), h_a + h_b in one launch
// ---------------------------------------------------------------------------
__global__ void prep_img_a_all(const float* __restrict__ Xa, const float* __restrict__ Xb) {
    int idx = blockIdx.x * blockDim.x + threadIdx.x;
    if (idx >= 2 * NN * 64) return;
    const float* X = (idx < NN * 64) ? Xa : Xb;
    char* img = (idx < NN * 64) ? g_ia : g_ib;
    int li = (idx < NN * 64) ? idx : idx - NN * 64;
    int m = li >> 6, kp = (li & 63) * 2;
    float2 v = *reinterpret_cast<const float2*>(X + (size_t)m * 128 + kp);
    uint32_t hi, lo;
    split2h(v.x, v.y, hi, lo);
    size_t tb = ((size_t)(m >> 7) * 4 + (kp >> 5)) * A_TILE;
    uint32_t byte = (uint32_t)((m & 127) * AROW + (kp & 31)) * 2;
    *reinterpret_cast<uint32_t*>(img + tb + byte) = hi;
    *reinterpret_cast<uint32_t*>(img + tb + A_PLANE + byte) = lo;
}

// ---------------------------------------------------------------------------
// fp16 2-term GEMM: C = (Ah+Al)@Bh (+bias)(+Res)(relu?)
// OUT_IMG: write A-image.  OUT_HALF: write fp16 (kp|vp table).
// ---------------------------------------------------------------------------
template<bool RES, bool RELU_OUT, bool OUT_IMG, bool OUT_HALF>
__global__ __launch_bounds__(256, 2) void tgemm6(
        const char* __restrict__ AImg, const char* __restrict__ BImg,
        const float* __restrict__ bias, const float* __restrict__ Rp,
        float* __restrict__ C, char* __restrict__ OutImg,
        int M, int Ncols, int K) {
    extern __shared__ __align__(16) char dsm[];
    const uint32_t sm0 = (uint32_t)__cvta_generic_to_shared(dsm);

    const int tid = threadIdx.x;
    const int wid = tid >> 5, lane = tid & 31;
    const int wm = wid & 3, wn = wid >> 2;
    const int wrow = wm * 32, wcol = wn * 64;
    const int row0 = blockIdx.y * 128;
    const int col0 = blockIdx.x * 128;
    const int ntiles = K >> 5;

    float acc[2][8][4];
#pragma unroll
    for (int mt = 0; mt < 2; mt++)
#pragma unroll
        for (int nt = 0; nt < 8; nt++)
#pragma unroll
            for (int r = 0; r < 4; r++) acc[mt][nt][r] = 0.f;

    const int lrow = (lane & 7) + ((lane >> 3) & 1) * 8;
    const int lcol = (lane >> 4) * 8;

    const char* abase = AImg + (size_t)blockIdx.y * ntiles * A_TILE;
    const char* bbase = BImg + (size_t)blockIdx.x * ntiles * B_TILE;

    // issue tile 0 (A 1280 + B 544 = 1824 16B chunks)
    {
        uint32_t dst = sm0;
#pragma unroll
        for (int i = 0; i < 8; i++) {
            int idx = tid + i * 256;
            if (idx < 1280)      cpa16(dst + idx * 16, abase + idx * 16);
            else if (idx < 1824) cpa16(dst + A_TILE + (idx - 1280) * 16, bbase + (idx - 1280) * 16);
        }
        CPA_COMMIT();
    }

    for (int t = 0; t < ntiles; t++) {
        const bool have_next = (t + 1 < ntiles);
        if (have_next) {
            const char* as = abase + (size_t)(t + 1) * A_TILE;
            const char* bs = bbase + (size_t)(t + 1) * B_TILE;
            uint32_t dst = sm0 + ((t + 1) & 1) * BUF_BYTES;
#pragma unroll
            for (int i = 0; i < 8; i++) {
                int idx = tid + i * 256;
                if (idx < 1280)      cpa16(dst + idx * 16, as + idx * 16);
                else if (idx < 1824) cpa16(dst + A_TILE + (idx - 1280) * 16, bs + (idx - 1280) * 16);
            }
            CPA_COMMIT();
            CPA_WAIT1();
        } else {
            CPA_WAIT0();
        }
        __syncthreads();

        const uint32_t cur = sm0 + (t & 1) * BUF_BYTES;
#pragma unroll
        for (int kc = 0; kc < 2; kc++) {
            const int k0 = kc * 16;
            uint32_t ahi[2][4], alo[2][4];
#pragma unroll
            for (int mt = 0; mt < 2; mt++) {
                uint32_t off = (uint32_t)((wrow + mt * 16 + lrow) * AROW + k0 + lcol) * 2;
                ldmx4(ahi[mt], cur + off);
                ldmx4(alo[mt], cur + A_PLANE + off);
            }
#pragma unroll
            for (int ng = 0; ng < 4; ng++) {
                uint32_t bf[4];
                uint32_t off = (uint32_t)((k0 + lrow) * BROW + wcol + ng * 16 + lcol) * 2;
                ldmx4t(bf, cur + A_TILE + off);
#pragma unroll
                for (int mt = 0; mt < 2; mt++) {
                    mma16(acc[mt][2 * ng],     ahi[mt], bf);
                    mma16(acc[mt][2 * ng],     alo[mt], bf);
                    mma16(acc[mt][2 * ng + 1], ahi[mt], bf + 2);
                    mma16(acc[mt][2 * ng + 1], alo[mt], bf + 2);
                }
            }
        }
        __syncthreads();
    }

    // epilogue
    const int okc = Ncols >> 5;
#pragma unroll
    for (int mt = 0; mt < 2; mt++) {
#pragma unroll
        for (int nt = 0; nt < 8; nt++) {
            int gr0 = row0 + wrow + mt * 16 + (lane >> 2);
            int gc  = col0 + wcol + nt * 8 + (lane & 3) * 2;
            float2 bb = *reinterpret_cast<const float2*>(&bias[gc]);
#pragma unroll
            for (int hh = 0; hh < 2; hh++) {
                int r = gr0 + hh * 8;
                if (r >= M) continue;
                float o0 = acc[mt][nt][hh * 2 + 0] + bb.x;
                float o1 = acc[mt][nt][hh * 2 + 1] + bb.y;
                if (RES) {
                    float2 rr = *reinterpret_cast<const float2*>(Rp + (size_t)r * Ncols + gc);
                    o0 += rr.x; o1 += rr.y;
                }
                if (RELU_OUT) { o0 = fmaxf(o0, 0.f); o1 = fmaxf(o1, 0.f); }
                if (OUT_IMG) {
                    uint32_t hi, lo;
                    split2h(o0, o1, hi, lo);
                    size_t tb = ((size_t)(r >> 7) * okc + (gc >> 5)) * A_TILE;
                    uint32_t byte = (uint32_t)((r & 127) * AROW + (gc & 31)) * 2;
                    *reinterpret_cast<uint32_t*>(OutImg + tb + byte) = hi;
                    *reinterpret_cast<uint32_t*>(OutImg + tb + A_PLANE + byte) = lo;
                } else if (OUT_HALF) {
                    __half2 hv = __floats2half2_rn(o0, o1);
                    *reinterpret_cast<__half2*>(reinterpret_cast<__half*>(C) + (size_t)r * Ncols + gc) = hv;
                } else {
                    *reinterpret_cast<float2*>(C + (size_t)r * Ncols + gc) = make_float2(o0, o1);
                }
            }
        }
    }
}

// ---------------------------------------------------------------------------
// Edge-index helpers
// ---------------------------------------------------------------------------
__global__ void zero_deg() {
    int i = blockIdx.x * blockDim.x + threadIdx.x;
    if (i == 0) g_i32 = 0;
    if (i < NSCAN) g_deg[i] = 0;
}
__global__ void detect_i32(const int* __restrict__ d) {
    int i = blockIdx.x * blockDim.x + threadIdx.x;
    if (i >= EE / 2) return;
    if (d[2 * i + 1] != 0) g_i32 = 1;
}
__device__ __forceinline__ int eidx(const void* p, int i, int is32) {
    return is32 ? ((const int*)p)[i] : (int)((const long long*)p)[i];
}
__global__ void count_deg(const void* __restrict__ dst, int r) {
    int i = blockIdx.x * blockDim.x + threadIdx.x;
    if (i >= EE) return;
    int is32 = g_i32;
    atomicAdd(&g_deg[r * NN + eidx(dst, i, is32)], 1);
}
__global__ void scatter_edges(const void* __restrict__ src, const void* __restrict__ dst, int r) {
    int i = blockIdx.x * blockDim.x + threadIdx.x;
    if (i >= EE) return;
    int is32 = g_i32;
    int d = eidx(dst, i, is32);
    int p = atomicAdd(&g_wpos[r * NN + d], 1);
    g_csr[p] = eidx(src, i, is32);
}

// ---------------------------------------------------------------------------
// Exclusive scan over g_deg[3N]
// ---------------------------------------------------------------------------
__global__ void scan1() {
    __shared__ int sh[SCAN_BS];
    int i = blockIdx.x * SCAN_BS + threadIdx.x;
    sh[threadIdx.x] = (i < NSCAN) ? g_deg[i] : 0;
    __syncthreads();
    for (int ofs = SCAN_BS / 2; ofs > 0; ofs >>= 1) {
        if (threadIdx.x < ofs) sh[threadIdx.x] += sh[threadIdx.x + ofs];
        __syncthreads();
    }
    if (threadIdx.x == 0) g_part[blockIdx.x] = sh[0];
}
__global__ void scan2() {
    __shared__ int a[512], b[512];
    int t = threadIdx.x;
    int v = (t < SCAN_NB) ? g_part[t] : 0;
    a[t] = v; __syncthreads();
    int* s = a; int* d = b;
    for (int ofs = 1; ofs < 512; ofs <<= 1) {
        int x = s[t];
        if (t >= ofs) x += s[t - ofs];
        d[t] = x; __syncthreads();
        int* tmp = s; s = d; d = tmp;
    }
    g_part_scan[t] = s[t] - v;
}
__global__ void scan3() {
    __shared__ int a[SCAN_BS], b[SCAN_BS];
    int t = threadIdx.x;
    int i = blockIdx.x * SCAN_BS + t;
    int v = (i < NSCAN) ? g_deg[i] : 0;
    a[t] = v; __syncthreads();
    int* s = a; int* d = b;
    for (int ofs = 1; ofs < SCAN_BS; ofs <<= 1) {
        int x = s[t];
        if (t >= ofs) x += s[t - ofs];
        d[t] = x; __syncthreads();
        int* tmp = s; s = d; d = tmp;
    }
    if (i < NSCAN) {
        int excl = s[t] - v + g_part_scan[blockIdx.x];
        g_off[i]  = excl;
        g_wpos[i] = excl;
    }
}

// ---------------------------------------------------------------------------
// Attention aggregation (fp16 kp|vp gather) -> writes relu(t) A-image
// ---------------------------------------------------------------------------
__device__ __forceinline__ void rel_accum(int node, int lane, int r,
                                          const __half* __restrict__ kvbuf,
                                          float4 q, float4& res) {
    int off = g_off[r * NN + node];
    int dg  = g_deg[r * NN + node];
    float4 acc = make_float4(0.f, 0.f, 0.f, 0.f);
    float z = 0.f;
    int e = 0;
    for (; e + 2 <= dg; e += 2) {
        int s0 = g_csr[off + e];
        int s1 = g_csr[off + e + 1];
        const __half* kv0 = kvbuf + (size_t)s0 * 256;
        const __half* kv1 = kvbuf + (size_t)s1 * 256;
        uint2 kp0u = *reinterpret_cast<const uint2*>(kv0 + lane * 4);
        uint2 kp1u = *reinterpret_cast<const uint2*>(kv1 + lane * 4);
        uint2 vp0u = *reinterpret_cast<const uint2*>(kv0 + 128 + lane * 4);
        uint2 vp1u = *reinterpret_cast<const uint2*>(kv1 + 128 + lane * 4);
        float2 k0a = __half22float2(*reinterpret_cast<__half2*>(&kp0u.x));
        float2 k0b = __half22float2(*reinterpret_cast<__half2*>(&kp0u.y));
        float2 k1a = __half22float2(*reinterpret_cast<__half2*>(&kp1u.x));
        float2 k1b = __half22float2(*reinterpret_cast<__half2*>(&kp1u.y));
        float p0 = q.x * k0a.x + q.y * k0a.y + q.z * k0b.x + q.w * k0b.y;
        float p1 = q.x * k1a.x + q.y * k1a.y + q.z * k1b.x + q.w * k1b.y;
        p0 += __shfl_xor_sync(0xffffffffu, p0, 1);
        p1 += __shfl_xor_sync(0xffffffffu, p1, 1);
        p0 += __shfl_xor_sync(0xffffffffu, p0, 2);
        p1 += __shfl_xor_sync(0xffffffffu, p1, 2);
        float e0 = expf(p0), e1 = expf(p1);
        z += e0 + e1;
        float2 v0a = __half22float2(*reinterpret_cast<__half2*>(&vp0u.x));
        float2 v0b = __half22float2(*reinterpret_cast<__half2*>(&vp0u.y));
        float2 v1a = __half22float2(*reinterpret_cast<__half2*>(&vp1u.x));
        float2 v1b = __half22float2(*reinterpret_cast<__half2*>(&vp1u.y));
        acc.x += e0 * v0a.x + e1 * v1a.x;
        acc.y += e0 * v0a.y + e1 * v1a.y;
        acc.z += e0 * v0b.x + e1 * v1b.x;
        acc.w += e0 * v0b.y + e1 * v1b.y;
    }
    if (e < dg) {
        int s = g_csr[off + e];
        const __half* kv = kvbuf + (size_t)s * 256;
        uint2 kpu = *reinterpret_cast<const uint2*>(kv + lane * 4);
        uint2 vpu = *reinterpret_cast<const uint2*>(kv + 128 + lane * 4);
        float2 ka = __half22float2(*reinterpret_cast<__half2*>(&kpu.x));
        float2 kb = __half22float2(*reinterpret_cast<__half2*>(&kpu.y));
        float p = q.x * ka.x + q.y * ka.y + q.z * kb.x + q.w * kb.y;
        p += __shfl_xor_sync(0xffffffffu, p, 1);
        p += __shfl_xor_sync(0xffffffffu, p, 2);
        float eh = expf(p);
        z += eh;
        float2 va = __half22float2(*reinterpret_cast<__half2*>(&vpu.x));
        float2 vb = __half22float2(*reinterpret_cast<__half2*>(&vpu.y));
        acc.x += eh * va.x; acc.y += eh * va.y;
        acc.z += eh * vb.x; acc.w += eh * vb.y;
    }
    if (z > 0.f) {
        float inv = 1.f / z;
        res.x += acc.x * inv; res.y += acc.y * inv;
        res.z += acc.z * inv; res.w += acc.w * inv;
    }
}

__device__ __forceinline__ void write_aimg4(char* img, int node, int lane, float4 v) {
    size_t tb = ((size_t)(node >> 7) * 4 + (lane >> 3)) * A_TILE;
    uint32_t byte = (uint32_t)((node & 127) * AROW + (lane & 7) * 4) * 2;
    uint32_t h0, l0, h1, l1;
    split2h(v.x, v.y, h0, l0);
    split2h(v.z, v.w, h1, l1);
    *reinterpret_cast<uint2*>(img + tb + byte) = make_uint2(h0, h1);
    *reinterpret_cast<uint2*>(img + tb + A_PLANE + byte) = make_uint2(l0, l1);
}

__global__ void agg_type_b() {
    int w = (blockIdx.x * blockDim.x + threadIdx.x) >> 5;
    if (w >= NN) return;
    int lane = threadIdx.x & 31;
    float4 q = *reinterpret_cast<const float4*>(g_qb + (size_t)w * 128 + lane * 4);
    float4 res = make_float4(0.f, 0.f, 0.f, 0.f);
    rel_accum(w, lane, 0, g_kv[0], q, res);
    res.x = fmaxf(res.x, 0.f); res.y = fmaxf(res.y, 0.f);
    res.z = fmaxf(res.z, 0.f); res.w = fmaxf(res.w, 0.f);
    write_aimg4(g_it[1], w, lane, res);
}

__global__ void agg_type_a() {
    int w = (blockIdx.x * blockDim.x + threadIdx.x) >> 5;
    if (w >= NN) return;
    int lane = threadIdx.x & 31;
    float4 q = *reinterpret_cast<const float4*>(g_qa + (size_t)w * 128 + lane * 4);
    float4 res = make_float4(0.f, 0.f, 0.f, 0.f);
    rel_accum(w, lane, 1, g_kv[1], q, res);
    rel_accum(w, lane, 2, g_kv[2], q, res);
    res.x = fmaxf(res.x, 0.f); res.y = fmaxf(res.y, 0.f);
    res.z = fmaxf(res.z, 0.f); res.w = fmaxf(res.w, 0.f);
    write_aimg4(g_it[0], w, lane, res);
}

// ---------------------------------------------------------------------------
// LayerNorm: reads fp32 g_x, writes A-image
// ---------------------------------------------------------------------------
__global__ void layernorm(const float* __restrict__ X, const float* __restrict__ gamma,
                          const float* __restrict__ beta, char* __restrict__ img) {
    int w = (blockIdx.x * blockDim.x + threadIdx.x) >> 5;
    if (w >= NN) return;
    int lane = threadIdx.x & 31;
    float4 v = *reinterpret_cast<const float4*>(X + (size_t)w * 128 + lane * 4);
    float s  = v.x + v.y + v.z + v.w;
    float s2 = v.x * v.x + v.y * v.y + v.z * v.z + v.w * v.w;
#pragma unroll
    for (int ofs = 16; ofs > 0; ofs >>= 1) {
        s  += __shfl_xor_sync(0xffffffffu, s, ofs);
        s2 += __shfl_xor_sync(0xffffffffu, s2, ofs);
    }
    float mu   = s * (1.f / 128.f);
    float var  = s2 * (1.f / 128.f) - mu * mu;
    float rstd = rsqrtf(var + 1e-5f);
    float4 g = *reinterpret_cast<const float4*>(gamma + lane * 4);
    float4 b = *reinterpret_cast<const float4*>(beta + lane * 4);
    float4 o;
    o.x = (v.x - mu) * rstd * g.x + b.x;
    o.y = (v.y - mu) * rstd * g.y + b.y;
    o.z = (v.z - mu) * rstd * g.z + b.z;
    o.w = (v.w - mu) * rstd * g.w + b.w;
    write_aimg4(img, w, lane, o);
}

// ---------------------------------------------------------------------------
// Launch
// ---------------------------------------------------------------------------
extern "C" void kernel_launch(void* const* d_in, const int* in_sizes, int n_in,
                              void* d_out, int out_size) {
    const float* h_a   = (const float*)d_in[0];
    const float* h_b   = (const float*)d_in[1];
    const float* Wk    = (const float*)d_in[2];
    const float* bk    = (const float*)d_in[3];
    const float* Wq    = (const float*)d_in[4];
    const float* bq    = (const float*)d_in[5];
    const float* Wv    = (const float*)d_in[6];
    const float* bv    = (const float*)d_in[7];
    const float* Wa    = (const float*)d_in[8];
    const float* ba    = (const float*)d_in[9];
    const float* gamma = (const float*)d_in[10];
    const float* beta  = (const float*)d_in[11];
    const float* W1    = (const float*)d_in[12];
    const float* b1    = (const float*)d_in[13];
    const float* W2    = (const float*)d_in[14];
    const float* b2    = (const float*)d_in[15];
    const float* pri   = (const float*)d_in[16];
    const float* att   = (const float*)d_in[17];
    const float* msg   = (const float*)d_in[18];
    const void* src0 = d_in[19]; const void* dst0 = d_in[20];
    const void* src1 = d_in[21]; const void* dst1 = d_in[22];
    const void* src2 = d_in[23]; const void* dst2 = d_in[24];
    float* out = (float*)d_out;

    float *p_qa, *p_qb, *p_x, *p_bkv;
    __half* p_kv;
    char *p_wimg, *p_ia, *p_ib, *p_it, *p_ix, *p_iff;
    cudaGetSymbolAddress((void**)&p_qa,   g_qa);
    cudaGetSymbolAddress((void**)&p_qb,   g_qb);
    cudaGetSymbolAddress((void**)&p_kv,   g_kv);
    cudaGetSymbolAddress((void**)&p_x,    g_x);
    cudaGetSymbolAddress((void**)&p_bkv,  g_bkv);
    cudaGetSymbolAddress((void**)&p_wimg, g_wimg);
    cudaGetSymbolAddress((void**)&p_ia,   g_ia);
    cudaGetSymbolAddress((void**)&p_ib,   g_ib);
    cudaGetSymbolAddress((void**)&p_it,   g_it);
    cudaGetSymbolAddress((void**)&p_ix,   g_ix);
    cudaGetSymbolAddress((void**)&p_iff,  g_iff);

    cudaFuncSetAttribute(tgemm6<false,false,false,false>, cudaFuncAttributeMaxDynamicSharedMemorySize, TG_SMEM);
    cudaFuncSetAttribute(tgemm6<false,false,false,true>,  cudaFuncAttributeMaxDynamicSharedMemorySize, TG_SMEM);
    cudaFuncSetAttribute(tgemm6<true,false,false,false>,  cudaFuncAttributeMaxDynamicSharedMemorySize, TG_SMEM);
    cudaFuncSetAttribute(tgemm6<false,true,true,false>,   cudaFuncAttributeMaxDynamicSharedMemorySize, TG_SMEM);

    const int gy = RB;
    const int eb = (EE + 255) / 256;
    const int wb = (NN * 32) / 256;

    // 0. reset + edge dtype detection
    zero_deg<<<(NSCAN + 255) / 256, 256>>>();
    detect_i32<<<(EE / 2 + 255) / 256, 256>>>((const int*)dst0);

    // 1. fused weights + images
    prep_weights<<<(6 * CIN * COUT + 255) / 256, 256>>>(Wk, bk, Wv, bv, pri, att, msg);
    prep_img_w_all<<<(425984 + 255) / 256, 256>>>(Wq, Wa, W1, W2);
    prep_img_a_all<<<(2 * NN * 64 + 255) / 256, 256>>>(h_a, h_b);

    // 2. projections (kv GEMMs emit fp16 kp|vp table)
    tgemm6<false,false,false,false><<<dim3(1, gy), 256, TG_SMEM>>>(p_ia, p_wimg + WQ0,  bq,       nullptr, p_qa, nullptr, NN, 128, 128);
    tgemm6<false,false,false,false><<<dim3(1, gy), 256, TG_SMEM>>>(p_ib, p_wimg + WQ1,  bq + 128, nullptr, p_qb, nullptr, NN, 128, 128);
    tgemm6<false,false,false,true><<<dim3(2, gy), 256, TG_SMEM>>>(p_ia, p_wimg + WKV0, p_bkv,       nullptr, (float*)p_kv,                            nullptr, NN, 256, 128);
    tgemm6<false,false,false,true><<<dim3(2, gy), 256, TG_SMEM>>>(p_ib, p_wimg + WKV1, p_bkv + 256, nullptr, (float*)(p_kv + (size_t)NN * 256),       nullptr, NN, 256, 128);
    tgemm6<false,false,false,true><<<dim3(2, gy), 256, TG_SMEM>>>(p_ia, p_wimg + WKV2, p_bkv + 512, nullptr, (float*)(p_kv + 2 * (size_t)NN * 256),   nullptr, NN, 256, 128);

    // 3. CSR build
    count_deg<<<eb, 256>>>(dst0, 0);
    count_deg<<<eb, 256>>>(dst1, 1);
    count_deg<<<eb, 256>>>(dst2, 2);
    scan1<<<SCAN_NB, SCAN_BS>>>();
    scan2<<<1, 512>>>();
    scan3<<<SCAN_NB, SCAN_BS>>>();
    scatter_edges<<<eb, 256>>>(src0, dst0, 0);
    scatter_edges<<<eb, 256>>>(src1, dst1, 1);
    scatter_edges<<<eb, 256>>>(src2, dst2, 2);

    // 4. attention aggregation -> relu(t) images
    agg_type_b<<<wb, 256>>>();
    agg_type_a<<<wb, 256>>>();

    // 5. per-type update
    for (int t = 0; t < 2; t++) {
        const float* hres = t ? h_b : h_a;
        tgemm6<true,false,false,false><<<dim3(1, gy), 256, TG_SMEM>>>(
            p_it + (size_t)t * AIMG_K128, p_wimg + (t ? WA1 : WA0),
            ba + t * 128, hres, p_x, nullptr, NN, 128, 128);
        layernorm<<<wb, 256>>>(p_x, gamma + t * 128, beta + t * 128, p_ix);
        tgemm6<false,true,true,false><<<dim3(4, gy), 256, TG_SMEM>>>(
            p_ix, p_wimg + (t ? W11 : W10),
            b1 + t * 512, nullptr, nullptr, p_iff, NN, 512, 128);
        tgemm6<false,false,false,false><<<dim3(1, gy), 256, TG_SMEM>>>(
            p_iff, p_wimg + (t ? W21 : W20),
            b2 + t * 128, nullptr, out + (size_t)t * NN * 128, nullptr, NN, 128, 512);
    }
}